// round 7
// baseline (speedup 1.0000x reference)
#include <cuda_runtime.h>

#define BB 4
#define HHH 64
#define LL 4096
#define EE 192
#define NNS 16
#define RR 6
#define KK 4
#define DM 96
#define BL (BB*LL)
#define C152 152
#define NCH 16
#define CHL 256   // LL/NCH

typedef unsigned long long u64;

// ------------------------- device scratch (no allocations) ------------------
__device__ float g_xx[BL*EE];
__device__ float g_z [BL*EE];
__device__ float g_xc[BL*EE];
__device__ float g_P [BL*C152];
__device__ float g_delta[16*EE*LL];
__device__ float g_du   [16*EE*LL];
__device__ float g_B4[16*LL*16];
__device__ float g_C4[16*LL*16];
__device__ float g_y [16*LL*EE];       // (bk, l, e)
__device__ float g_ym[BL*EE];
// decoupled-lookback carries: cidx in [0,384), chunk in [0,16)
__device__ float g_carry[384*NCH*128];
__device__ int   g_cflag[384*NCH];

__device__ __forceinline__ float ex2f(float x){
    float y; asm("ex2.approx.f32 %0, %1;" : "=f"(y) : "f"(x)); return y;
}
__device__ __forceinline__ float siluf(float x){
    return x / (1.f + __expf(-x));
}
__device__ __forceinline__ float softplusf(float x){
    return fmaxf(x, 0.f) + __logf(1.f + __expf(-fabsf(x)));
}
__device__ __forceinline__ u64 fma2(u64 a, u64 b, u64 c){
    u64 d; asm("fma.rn.f32x2 %0, %1, %2, %3;" : "=l"(d) : "l"(a), "l"(b), "l"(c));
    return d;
}
__device__ __forceinline__ u64 pack2(float x, float y){
    u64 d; asm("mov.b64 %0, {%1, %2};" : "=l"(d) : "f"(x), "f"(y));
    return d;
}
__device__ __forceinline__ void unpack2(u64 v, float& lo, float& hi){
    asm("mov.b64 {%0, %1}, %2;" : "=f"(lo), "=f"(hi) : "l"(v));
}

// ------------------------- tiled GEMM: out[m,n] = sum_k X[m,k]*W[n,k] -------
// 128x64 tile, 256 threads, 8x4 micro-tile, f32x2 packed accumulation
template<int KD, int MODE>
__global__ void __launch_bounds__(256)
k_gemm(const float* __restrict__ Xp, const float* __restrict__ W,
       float* __restrict__ Out, int Nn)
{
    __shared__ float Xs[32][132];
    __shared__ float Ws[32][68];
    const float* __restrict__ X = (MODE==0) ? (const float*)g_xc
                                : (MODE==2) ? (const float*)g_ym : Xp;
    const int m0 = blockIdx.x * 128;
    const int n0 = blockIdx.y * 64;
    const int t  = threadIdx.x;
    const int ty = t >> 4, tx = t & 15;
    u64 acc2[4][4];
    #pragma unroll
    for (int i=0;i<4;i++)
        #pragma unroll
        for (int j=0;j<4;j++) acc2[i][j] = 0ull;

    const int lc4 = (t & 7) * 4;
    const int lr0 = t >> 3;

    for (int kc = 0; kc < KD/32; kc++){
        __syncthreads();
        #pragma unroll
        for (int i = 0; i < 4; i++){
            int r = lr0 + 32*i;
            float4 v = *(const float4*)&X[(m0+r)*KD + kc*32 + lc4];
            Xs[lc4+0][r] = v.x; Xs[lc4+1][r] = v.y;
            Xs[lc4+2][r] = v.z; Xs[lc4+3][r] = v.w;
        }
        #pragma unroll
        for (int i = 0; i < 2; i++){
            int r = lr0 + 32*i;
            int nr = n0 + r;
            float4 v = make_float4(0.f,0.f,0.f,0.f);
            if (nr < Nn) v = *(const float4*)&W[nr*KD + kc*32 + lc4];
            Ws[lc4+0][r] = v.x; Ws[lc4+1][r] = v.y;
            Ws[lc4+2][r] = v.z; Ws[lc4+3][r] = v.w;
        }
        __syncthreads();
        #pragma unroll
        for (int k = 0; k < 32; k++){
            const u64* xp = (const u64*)&Xs[k][ty*8];
            u64 x2[4] = {xp[0], xp[1], xp[2], xp[3]};
            float4 wv = *(const float4*)&Ws[k][tx*4];
            u64 w2[4] = {pack2(wv.x,wv.x), pack2(wv.y,wv.y),
                         pack2(wv.z,wv.z), pack2(wv.w,wv.w)};
            #pragma unroll
            for (int i=0;i<4;i++)
                #pragma unroll
                for (int j=0;j<4;j++) acc2[i][j] = fma2(x2[i], w2[j], acc2[i][j]);
        }
    }
    #pragma unroll
    for (int i=0;i<4;i++){
        #pragma unroll
        for (int j=0;j<4;j++){
            float lo, hi;
            unpack2(acc2[i][j], lo, hi);
            int n = n0 + tx*4 + j;
            int mA = m0 + ty*8 + 2*i;
            #pragma unroll
            for (int pp = 0; pp < 2; pp++){
                int m = mA + pp;
                float v = pp ? hi : lo;
                if (MODE == 1){
                    if (n < EE) g_xx[m*EE + n] = v;
                    else        g_z [m*EE + n - EE] = siluf(v);
                } else if (MODE == 0){
                    if (n < Nn) g_P[m*C152 + n] = v;
                } else {
                    if (n < Nn) Out[m*Nn + n] = v;
                }
            }
        }
    }
}

// ------------------------- depthwise 3x3 conv + bias + silu -----------------
__global__ void __launch_bounds__(256) k_conv(const float* __restrict__ cw, const float* __restrict__ cb)
{
    __shared__ float xs_s[3][64][48];
    __shared__ float cw_s[48][9];
    const int e0 = blockIdx.x * 48;
    const int h  = blockIdx.y;
    const int b  = blockIdx.z;
    const int t  = threadIdx.x;

    for (int idx = t; idx < 3*64*48; idx += 256){
        int row = idx / (64*48);
        int rem = idx - row*(64*48);
        int w  = rem / 48;
        int ec = rem - w*48;
        int hh = h + row - 1;
        float v = 0.f;
        if (hh >= 0 && hh < HHH)
            v = g_xx[(b*LL + hh*64 + w)*EE + e0 + ec];
        xs_s[row][w][ec] = v;
    }
    for (int idx = t; idx < 48*9; idx += 256){
        int ec = idx / 9, q = idx - ec*9;
        cw_s[ec][q] = cw[(e0+ec)*9 + q];
    }
    __syncthreads();

    for (int o = t; o < 64*48; o += 256){
        int w  = o / 48;
        int ec = o - w*48;
        float acc = cb[e0+ec];
        #pragma unroll
        for (int dh = 0; dh < 3; dh++){
            #pragma unroll
            for (int dw = 0; dw < 3; dw++){
                int ww = w + dw - 1;
                if (ww >= 0 && ww < 64)
                    acc = fmaf(xs_s[dh][ww][ec], cw_s[ec][dh*3+dw], acc);
            }
        }
        g_xc[(b*LL + h*64 + w)*EE + e0 + ec] = siluf(acc);
    }
}

// ------------------------- prep: delta/du + B4/C4 + flag reset --------------
// B4/C4 slot layout per l: np = lj*4 + s  <->  state n = 4*s + lj
__global__ void __launch_bounds__(256) k_prep(const float* __restrict__ dtw, const float* __restrict__ dtb)
{
    __shared__ float Pt[32][39];
    __shared__ float xr[32][193];
    __shared__ float dtws[EE*RR];
    __shared__ float dtbs[EE];
    __shared__ int   clm[32];
    const int bid = blockIdx.x;
    const int lt = bid & 127;
    const int k  = (bid >> 7) & 3;
    const int b  = bid >> 9;
    const int l0 = lt * 32;
    const int t  = threadIdx.x;

    // reset lookback flags for the scan kernel (stream-ordered before k_scan)
    if (bid < 24) g_cflag[bid*256 + t] = 0;

    if (t < 32){
        int l = l0 + t, cl;
        if (k == 0)      cl = l;
        else if (k == 1) cl = (l & 63)*64 + (l >> 6);
        else if (k == 2) cl = (LL-1) - l;
        else { int lp = (LL-1) - l; cl = (lp & 63)*64 + (lp >> 6); }
        clm[t] = cl;
    }
    for (int idx = t; idx < EE*RR; idx += 256) dtws[idx] = dtw[k*EE*RR + idx];
    for (int idx = t; idx < EE;    idx += 256) dtbs[idx] = dtb[k*EE + idx];
    __syncthreads();
    for (int idx = t; idx < 32*38; idx += 256){
        int r = idx / 38, c = idx - r*38;
        Pt[r][c] = g_P[(b*LL + clm[r])*C152 + k*38 + c];
    }
    for (int idx = t; idx < 32*48; idx += 256){
        int r = idx / 48, c = idx - r*48;
        float4 v = *(const float4*)&g_xc[(b*LL + clm[r])*EE + c*4];
        xr[r][c*4+0] = v.x; xr[r][c*4+1] = v.y;
        xr[r][c*4+2] = v.z; xr[r][c*4+3] = v.w;
    }
    __syncthreads();

    const int warp = t >> 5, lane = t & 31;
    const int bk = b*KK + k;
    for (int e = warp; e < EE; e += 8){
        float acc = dtbs[e];
        #pragma unroll
        for (int r = 0; r < RR; r++) acc = fmaf(Pt[lane][r], dtws[e*RR + r], acc);
        float dl = softplusf(acc);
        float u  = xr[lane][e];
        int idx = (bk*EE + e)*LL + l0 + lane;
        g_delta[idx] = dl;
        g_du[idx]    = dl * u;
    }
    for (int idx = t; idx < 32*16; idx += 256){
        int pos = idx >> 4, np = idx & 15;
        int n = 4*(np & 3) + (np >> 2);     // state index for slot np
        int o = (bk*LL + l0 + pos)*16 + np;
        g_B4[o] = Pt[pos][6  + n];
        g_C4[o] = Pt[pos][22 + n];
    }
}

// ------------------------- single-pass scan with decoupled lookback ---------
// block 2i = chunks 0..7 of cidx i, block 2i+1 = chunks 8..15.
// Dependencies point only to lower blockIdx -> no deadlock in any residency.
// warp = 8 chains (same bk); 4 lanes/chain, 4 states/lane.
__global__ void __launch_bounds__(256) k_scan(const float* __restrict__ A_logs)
{
    const int warp = threadIdx.x >> 5;
    const int lane = threadIdx.x & 31;
    const int cidx  = blockIdx.x >> 1;
    const int chunk = ((blockIdx.x & 1) << 3) + warp;
    const int bk = cidx / 24;
    const int e  = (cidx - bk*24)*8 + (lane >> 2);
    const int lj = lane & 3;
    const int k  = bk & 3;

    const float L2E = 1.4426950408889634f;
    float am[4]; bool okl = true;
    #pragma unroll
    for (int s = 0; s < 4; s++){
        int n = 4*s + lj;
        float av = -__expf(A_logs[(k*EE + e)*NNS + n]);
        am[s] = av * L2E;
        okl &= fabsf(av + (float)(n+1)) < 1e-4f * (float)(n+1);
    }
    const bool ok = __all_sync(0xffffffffu, okl);

    const int ch = bk*EE + e;
    const long chb = (long)ch*LL;
    const float* __restrict__ pd = g_delta + chb;
    const float* __restrict__ pu = g_du    + chb;
    const float* __restrict__ pb = g_B4 + (long)bk*LL*16;
    const float* __restrict__ pc = g_C4 + (long)bk*LL*16;
    float* __restrict__ py = g_y + (long)bk*LL*EE;

    const int l0 = chunk*CHL;
    const float am0 = am[0];

    float h0=0.f, h1=0.f, h2=0.f, h3=0.f, sdd = 0.f;

    // ---- sweep 1: local (h_fin, Sdd); not needed for the last chunk ----
    if (chunk < NCH-1){
        if (ok){
            for (int l = l0; l < l0 + CHL; l += 4){
                float4 d4 = *(const float4*)(pd + l);
                float4 u4 = *(const float4*)(pu + l);
                float dd[4] = {d4.x, d4.y, d4.z, d4.w};
                float uu[4] = {u4.x, u4.y, u4.z, u4.w};
                #pragma unroll
                for (int s = 0; s < 4; s++){
                    float4 b4 = *(const float4*)(pb + (l+s)*16 + lj*4);
                    float t  = ex2f(dd[s]*am0);
                    float q4 = __shfl_sync(0xffffffffu, t, 3, 4);
                    float dA1 = t*q4, dA2 = dA1*q4, dA3 = dA2*q4;
                    float us = uu[s];
                    h0 = fmaf(t,   h0, us*b4.x);
                    h1 = fmaf(dA1, h1, us*b4.y);
                    h2 = fmaf(dA2, h2, us*b4.z);
                    h3 = fmaf(dA3, h3, us*b4.w);
                }
                sdd += dd[0] + dd[1] + dd[2] + dd[3];
            }
        } else {
            #pragma unroll 1
            for (int l = l0; l < l0 + CHL; l += 4){
                float4 d4 = *(const float4*)(pd + l);
                float4 u4 = *(const float4*)(pu + l);
                float dd[4] = {d4.x, d4.y, d4.z, d4.w};
                float uu[4] = {u4.x, u4.y, u4.z, u4.w};
                #pragma unroll
                for (int s = 0; s < 4; s++){
                    float4 b4 = *(const float4*)(pb + (l+s)*16 + lj*4);
                    float us = uu[s];
                    h0 = fmaf(ex2f(dd[s]*am[0]), h0, us*b4.x);
                    h1 = fmaf(ex2f(dd[s]*am[1]), h1, us*b4.y);
                    h2 = fmaf(ex2f(dd[s]*am[2]), h2, us*b4.z);
                    h3 = fmaf(ex2f(dd[s]*am[3]), h3, us*b4.w);
                }
                sdd += dd[0] + dd[1] + dd[2] + dd[3];
            }
        }
    }

    // ---- acquire incoming carry ----
    float4 hin = make_float4(0.f, 0.f, 0.f, 0.f);
    if (chunk > 0){
        const int fi = cidx*NCH + chunk - 1;
        volatile int* fp = g_cflag + fi;
        while (*fp == 0) { }
        __threadfence();
        volatile float* cp = g_carry + (long)fi*128 + lane*4;
        hin.x = cp[0]; hin.y = cp[1]; hin.z = cp[2]; hin.w = cp[3];
    }

    // ---- publish outgoing carry ----
    if (chunk < NCH-1){
        float e0 = ex2f(sdd*am[0]);
        float e1 = ex2f(sdd*am[1]);
        float e2 = ex2f(sdd*am[2]);
        float e3 = ex2f(sdd*am[3]);
        const int fo = cidx*NCH + chunk;
        volatile float* cp = g_carry + (long)fo*128 + lane*4;
        cp[0] = fmaf(e0, hin.x, h0);
        cp[1] = fmaf(e1, hin.y, h1);
        cp[2] = fmaf(e2, hin.z, h2);
        cp[3] = fmaf(e3, hin.w, h3);
        __threadfence();
        __syncwarp();
        if (lane == 0) *(volatile int*)(g_cflag + fo) = 1;
    }

    // ---- sweep 2: full scan with y output ----
    h0 = hin.x; h1 = hin.y; h2 = hin.z; h3 = hin.w;
    if (ok){
        for (int l = l0; l < l0 + CHL; l += 4){
            float4 d4 = *(const float4*)(pd + l);
            float4 u4 = *(const float4*)(pu + l);
            float dd[4] = {d4.x, d4.y, d4.z, d4.w};
            float uu[4] = {u4.x, u4.y, u4.z, u4.w};
            float ysv = 0.f;
            #pragma unroll
            for (int s = 0; s < 4; s++){
                float4 b4 = *(const float4*)(pb + (l+s)*16 + lj*4);
                float4 c4 = *(const float4*)(pc + (l+s)*16 + lj*4);
                float t  = ex2f(dd[s]*am0);
                float q4 = __shfl_sync(0xffffffffu, t, 3, 4);
                float dA1 = t*q4, dA2 = dA1*q4, dA3 = dA2*q4;
                float us = uu[s];
                h0 = fmaf(t,   h0, us*b4.x);
                h1 = fmaf(dA1, h1, us*b4.y);
                h2 = fmaf(dA2, h2, us*b4.z);
                h3 = fmaf(dA3, h3, us*b4.w);
                float p = h0*c4.x;
                p = fmaf(h1, c4.y, p);
                p = fmaf(h2, c4.z, p);
                p = fmaf(h3, c4.w, p);
                p += __shfl_xor_sync(0xffffffffu, p, 1);
                p += __shfl_xor_sync(0xffffffffu, p, 2);
                if (lj == s) ysv = p;
            }
            py[(long)(l + lj)*EE + e] = ysv;
        }
    } else {
        #pragma unroll 1
        for (int l = l0; l < l0 + CHL; l += 4){
            float4 d4 = *(const float4*)(pd + l);
            float4 u4 = *(const float4*)(pu + l);
            float dd[4] = {d4.x, d4.y, d4.z, d4.w};
            float uu[4] = {u4.x, u4.y, u4.z, u4.w};
            float ysv = 0.f;
            #pragma unroll
            for (int s = 0; s < 4; s++){
                float4 b4 = *(const float4*)(pb + (l+s)*16 + lj*4);
                float4 c4 = *(const float4*)(pc + (l+s)*16 + lj*4);
                float us = uu[s];
                h0 = fmaf(ex2f(dd[s]*am[0]), h0, us*b4.x);
                h1 = fmaf(ex2f(dd[s]*am[1]), h1, us*b4.y);
                h2 = fmaf(ex2f(dd[s]*am[2]), h2, us*b4.z);
                h3 = fmaf(ex2f(dd[s]*am[3]), h3, us*b4.w);
                float p = h0*c4.x;
                p = fmaf(h1, c4.y, p);
                p = fmaf(h2, c4.z, p);
                p = fmaf(h3, c4.w, p);
                p += __shfl_xor_sync(0xffffffffu, p, 1);
                p += __shfl_xor_sync(0xffffffffu, p, 2);
                if (lj == s) ysv = p;
            }
            py[(long)(l + lj)*EE + e] = ysv;
        }
    }
}

// ------------------------- merge + D*xc + LayerNorm + gate ------------------
// block = 32 l x 8 threads; all reads are contiguous 192-float rows
__global__ void __launch_bounds__(256) k_merge(const float* __restrict__ Ds, const float* __restrict__ gamma,
                        const float* __restrict__ beta)
{
    __shared__ float sumD[EE];
    const int l0 = blockIdx.x * 32;
    const int b  = blockIdx.y;
    const int t  = threadIdx.x;
    if (t < EE) sumD[t] = Ds[t] + Ds[EE + t] + Ds[2*EE + t] + Ds[3*EE + t];
    __syncthreads();

    const int li = t >> 3, ts = t & 7;
    const int l  = l0 + li;
    const int lw = (l & 63)*64 + (l >> 6);

    const float* __restrict__ y0p = g_y + ((long)(b*4 + 0)*LL + l)*EE;
    const float* __restrict__ y1p = g_y + ((long)(b*4 + 1)*LL + lw)*EE;
    const float* __restrict__ y2p = g_y + ((long)(b*4 + 2)*LL + (LL-1-l))*EE;
    const float* __restrict__ y3p = g_y + ((long)(b*4 + 3)*LL + (LL-1-lw))*EE;
    const float* __restrict__ xcp = g_xc + (long)(b*LL + l)*EE;
    const float* __restrict__ zp  = g_z  + (long)(b*LL + l)*EE;
    float* __restrict__ ymp = g_ym + (long)(b*LL + l)*EE;

    float v[6][4];
    float s1 = 0.f, s2 = 0.f;
    #pragma unroll
    for (int m = 0; m < 6; m++){
        int e4 = (ts + 8*m)*4;
        float4 a0 = *(const float4*)(y0p + e4);
        float4 a1 = *(const float4*)(y1p + e4);
        float4 a2 = *(const float4*)(y2p + e4);
        float4 a3 = *(const float4*)(y3p + e4);
        float4 xc = *(const float4*)(xcp + e4);
        float4 sd = *(const float4*)(&sumD[e4]);
        v[m][0] = a0.x + a1.x + a2.x + a3.x + sd.x*xc.x;
        v[m][1] = a0.y + a1.y + a2.y + a3.y + sd.y*xc.y;
        v[m][2] = a0.z + a1.z + a2.z + a3.z + sd.z*xc.z;
        v[m][3] = a0.w + a1.w + a2.w + a3.w + sd.w*xc.w;
        #pragma unroll
        for (int q = 0; q < 4; q++){ s1 += v[m][q]; s2 += v[m][q]*v[m][q]; }
    }
    #pragma unroll
    for (int o = 1; o < 8; o <<= 1){
        s1 += __shfl_xor_sync(0xffffffffu, s1, o);
        s2 += __shfl_xor_sync(0xffffffffu, s2, o);
    }
    const float inv = 1.f / (float)EE;
    float mu = s1 * inv;
    float var = s2 * inv - mu*mu;
    float rstd = rsqrtf(var + 1e-5f);

    #pragma unroll
    for (int m = 0; m < 6; m++){
        int e4 = (ts + 8*m)*4;
        float4 gm = *(const float4*)(gamma + e4);
        float4 bt = *(const float4*)(beta + e4);
        float4 zz = *(const float4*)(zp + e4);
        float4 o4;
        o4.x = ((v[m][0]-mu)*rstd*gm.x + bt.x) * zz.x;
        o4.y = ((v[m][1]-mu)*rstd*gm.y + bt.y) * zz.y;
        o4.z = ((v[m][2]-mu)*rstd*gm.z + bt.z) * zz.z;
        o4.w = ((v[m][3]-mu)*rstd*gm.w + bt.w) * zz.w;
        *(float4*)(ymp + e4) = o4;
    }
}

// ------------------------- launcher -----------------------------------------
extern "C" void kernel_launch(void* const* d_in, const int* in_sizes, int n_in,
                              void* d_out, int out_size)
{
    const float* x    = (const float*)d_in[0];
    const float* ipw  = (const float*)d_in[1];
    const float* cw   = (const float*)d_in[2];
    const float* cb   = (const float*)d_in[3];
    const float* xpw  = (const float*)d_in[4];
    const float* dtw  = (const float*)d_in[5];
    const float* dtb  = (const float*)d_in[6];
    const float* alog = (const float*)d_in[7];
    const float* Ds   = (const float*)d_in[8];
    const float* lng  = (const float*)d_in[9];
    const float* lnb  = (const float*)d_in[10];
    const float* opw  = (const float*)d_in[11];
    float* out = (float*)d_out;

    k_gemm<DM, 1><<<dim3(128, 6), 256>>>(x, ipw, nullptr, 2*EE);
    k_conv<<<dim3(4, 64, BB), 256>>>(cw, cb);
    k_gemm<EE, 0><<<dim3(128, 3), 256>>>(nullptr, xpw, nullptr, C152);
    k_prep<<<BB*KK*128, 256>>>(dtw, dtb);
    k_scan<<<768, 256>>>(alog);
    k_merge<<<dim3(128, BB), 256>>>(Ds, lng, lnb);
    k_gemm<EE, 2><<<dim3(128, 2), 256>>>(nullptr, opw, out, DM);
}

// round 8
// speedup vs baseline: 1.0430x; 1.0430x over previous
#include <cuda_runtime.h>

#define BB 4
#define HHH 64
#define LL 4096
#define EE 192
#define NNS 16
#define RR 6
#define KK 4
#define DM 96
#define BL (BB*LL)
#define C152 152
#define NCH 16
#define CHL 256   // LL/NCH

typedef unsigned long long u64;

// ------------------------- device scratch (no allocations) ------------------
__device__ float g_xx[BL*EE];
__device__ float g_z [BL*EE];
__device__ float g_xc[BL*EE];
__device__ float g_P [BL*C152];
__device__ float g_delta[16*EE*LL];
__device__ float g_du   [16*EE*LL];
__device__ float g_B4[16*LL*16];
__device__ float g_C4[16*LL*16];
__device__ float g_y [16*LL*EE];       // (bk, l, e)
__device__ float g_ym[BL*EE];

__device__ __forceinline__ float ex2f(float x){
    float y; asm("ex2.approx.f32 %0, %1;" : "=f"(y) : "f"(x)); return y;
}
__device__ __forceinline__ float siluf(float x){
    return x / (1.f + __expf(-x));
}
__device__ __forceinline__ float softplusf(float x){
    return fmaxf(x, 0.f) + __logf(1.f + __expf(-fabsf(x)));
}
__device__ __forceinline__ u64 fma2(u64 a, u64 b, u64 c){
    u64 d; asm("fma.rn.f32x2 %0, %1, %2, %3;" : "=l"(d) : "l"(a), "l"(b), "l"(c));
    return d;
}
__device__ __forceinline__ u64 pack2(float x, float y){
    u64 d; asm("mov.b64 %0, {%1, %2};" : "=l"(d) : "f"(x), "f"(y));
    return d;
}
__device__ __forceinline__ void unpack2(u64 v, float& lo, float& hi){
    asm("mov.b64 {%0, %1}, %2;" : "=f"(lo), "=f"(hi) : "l"(v));
}

// ------------------------- tiled GEMM: out[m,n] = sum_k X[m,k]*W[n,k] -------
// 128x64 tile, 256 threads, 8x4 micro-tile, f32x2 packed accumulation
template<int KD, int MODE>
__global__ void __launch_bounds__(256)
k_gemm(const float* __restrict__ Xp, const float* __restrict__ W,
       float* __restrict__ Out, int Nn)
{
    __shared__ float Xs[32][132];
    __shared__ float Ws[32][68];
    const float* __restrict__ X = (MODE==0) ? (const float*)g_xc
                                : (MODE==2) ? (const float*)g_ym : Xp;
    const int m0 = blockIdx.x * 128;
    const int n0 = blockIdx.y * 64;
    const int t  = threadIdx.x;
    const int ty = t >> 4, tx = t & 15;
    u64 acc2[4][4];
    #pragma unroll
    for (int i=0;i<4;i++)
        #pragma unroll
        for (int j=0;j<4;j++) acc2[i][j] = 0ull;

    const int lc4 = (t & 7) * 4;
    const int lr0 = t >> 3;

    for (int kc = 0; kc < KD/32; kc++){
        __syncthreads();
        #pragma unroll
        for (int i = 0; i < 4; i++){
            int r = lr0 + 32*i;
            float4 v = *(const float4*)&X[(m0+r)*KD + kc*32 + lc4];
            Xs[lc4+0][r] = v.x; Xs[lc4+1][r] = v.y;
            Xs[lc4+2][r] = v.z; Xs[lc4+3][r] = v.w;
        }
        #pragma unroll
        for (int i = 0; i < 2; i++){
            int r = lr0 + 32*i;
            int nr = n0 + r;
            float4 v = make_float4(0.f,0.f,0.f,0.f);
            if (nr < Nn) v = *(const float4*)&W[nr*KD + kc*32 + lc4];
            Ws[lc4+0][r] = v.x; Ws[lc4+1][r] = v.y;
            Ws[lc4+2][r] = v.z; Ws[lc4+3][r] = v.w;
        }
        __syncthreads();
        #pragma unroll
        for (int k = 0; k < 32; k++){
            const u64* xp = (const u64*)&Xs[k][ty*8];
            u64 x2[4] = {xp[0], xp[1], xp[2], xp[3]};
            float4 wv = *(const float4*)&Ws[k][tx*4];
            u64 w2[4] = {pack2(wv.x,wv.x), pack2(wv.y,wv.y),
                         pack2(wv.z,wv.z), pack2(wv.w,wv.w)};
            #pragma unroll
            for (int i=0;i<4;i++)
                #pragma unroll
                for (int j=0;j<4;j++) acc2[i][j] = fma2(x2[i], w2[j], acc2[i][j]);
        }
    }
    #pragma unroll
    for (int i=0;i<4;i++){
        #pragma unroll
        for (int j=0;j<4;j++){
            float lo, hi;
            unpack2(acc2[i][j], lo, hi);
            int n = n0 + tx*4 + j;
            int mA = m0 + ty*8 + 2*i;
            #pragma unroll
            for (int pp = 0; pp < 2; pp++){
                int m = mA + pp;
                float v = pp ? hi : lo;
                if (MODE == 1){
                    if (n < EE) g_xx[m*EE + n] = v;
                    else        g_z [m*EE + n - EE] = siluf(v);
                } else if (MODE == 0){
                    if (n < Nn) g_P[m*C152 + n] = v;
                } else {
                    if (n < Nn) Out[m*Nn + n] = v;
                }
            }
        }
    }
}

// ------------------------- depthwise 3x3 conv + bias + silu -----------------
__global__ void __launch_bounds__(256) k_conv(const float* __restrict__ cw, const float* __restrict__ cb)
{
    __shared__ float xs_s[3][64][48];
    __shared__ float cw_s[48][9];
    const int e0 = blockIdx.x * 48;
    const int h  = blockIdx.y;
    const int b  = blockIdx.z;
    const int t  = threadIdx.x;

    for (int idx = t; idx < 3*64*48; idx += 256){
        int row = idx / (64*48);
        int rem = idx - row*(64*48);
        int w  = rem / 48;
        int ec = rem - w*48;
        int hh = h + row - 1;
        float v = 0.f;
        if (hh >= 0 && hh < HHH)
            v = g_xx[(b*LL + hh*64 + w)*EE + e0 + ec];
        xs_s[row][w][ec] = v;
    }
    for (int idx = t; idx < 48*9; idx += 256){
        int ec = idx / 9, q = idx - ec*9;
        cw_s[ec][q] = cw[(e0+ec)*9 + q];
    }
    __syncthreads();

    for (int o = t; o < 64*48; o += 256){
        int w  = o / 48;
        int ec = o - w*48;
        float acc = cb[e0+ec];
        #pragma unroll
        for (int dh = 0; dh < 3; dh++){
            #pragma unroll
            for (int dw = 0; dw < 3; dw++){
                int ww = w + dw - 1;
                if (ww >= 0 && ww < 64)
                    acc = fmaf(xs_s[dh][ww][ec], cw_s[ec][dh*3+dw], acc);
            }
        }
        g_xc[(b*LL + h*64 + w)*EE + e0 + ec] = siluf(acc);
    }
}

// ------------------------- prep: delta/du + B4/C4 ---------------------------
// B4/C4 slot layout per l: np = lj*4 + s  <->  state n = 4*s + lj
__global__ void __launch_bounds__(256) k_prep(const float* __restrict__ dtw, const float* __restrict__ dtb)
{
    __shared__ float Pt[32][39];
    __shared__ float xr[32][193];
    __shared__ float dtws[EE*RR];
    __shared__ float dtbs[EE];
    __shared__ int   clm[32];
    const int bid = blockIdx.x;
    const int lt = bid & 127;
    const int k  = (bid >> 7) & 3;
    const int b  = bid >> 9;
    const int l0 = lt * 32;
    const int t  = threadIdx.x;

    if (t < 32){
        int l = l0 + t, cl;
        if (k == 0)      cl = l;
        else if (k == 1) cl = (l & 63)*64 + (l >> 6);
        else if (k == 2) cl = (LL-1) - l;
        else { int lp = (LL-1) - l; cl = (lp & 63)*64 + (lp >> 6); }
        clm[t] = cl;
    }
    for (int idx = t; idx < EE*RR; idx += 256) dtws[idx] = dtw[k*EE*RR + idx];
    for (int idx = t; idx < EE;    idx += 256) dtbs[idx] = dtb[k*EE + idx];
    __syncthreads();
    for (int idx = t; idx < 32*38; idx += 256){
        int r = idx / 38, c = idx - r*38;
        Pt[r][c] = g_P[(b*LL + clm[r])*C152 + k*38 + c];
    }
    for (int idx = t; idx < 32*48; idx += 256){
        int r = idx / 48, c = idx - r*48;
        float4 v = *(const float4*)&g_xc[(b*LL + clm[r])*EE + c*4];
        xr[r][c*4+0] = v.x; xr[r][c*4+1] = v.y;
        xr[r][c*4+2] = v.z; xr[r][c*4+3] = v.w;
    }
    __syncthreads();

    const int warp = t >> 5, lane = t & 31;
    const int bk = b*KK + k;
    for (int e = warp; e < EE; e += 8){
        float acc = dtbs[e];
        #pragma unroll
        for (int r = 0; r < RR; r++) acc = fmaf(Pt[lane][r], dtws[e*RR + r], acc);
        float dl = softplusf(acc);
        float u  = xr[lane][e];
        int idx = (bk*EE + e)*LL + l0 + lane;
        g_delta[idx] = dl;
        g_du[idx]    = dl * u;
    }
    for (int idx = t; idx < 32*16; idx += 256){
        int pos = idx >> 4, np = idx & 15;
        int n = 4*(np & 3) + (np >> 2);     // state index for slot np
        int o = (bk*LL + l0 + pos)*16 + np;
        g_B4[o] = Pt[pos][6  + n];
        g_C4[o] = Pt[pos][22 + n];
    }
}

// ------------------------- fused scan: block = 1 chain-group x 16 chunks ----
// 512 threads = 16 warps; warp = chunk; 8 chains/warp, 4 lanes/chain, 4 st/lane
// sweep1 (chunks 0..14) -> smem carries -> in-block propagate -> sweep2
__global__ void __launch_bounds__(512) k_scan(const float* __restrict__ A_logs)
{
    __shared__ float hf_s [NCH][128];
    __shared__ float hi_s [NCH][128];
    __shared__ float sdd_s[NCH][8];

    const int warp = threadIdx.x >> 5;     // chunk
    const int lane = threadIdx.x & 31;
    const int cidx = blockIdx.x;           // [0, 384)
    const int chunk = warp;
    const int bk = cidx / 24;
    const int e  = (cidx - bk*24)*8 + (lane >> 2);
    const int lj = lane & 3;
    const int k  = bk & 3;

    const float L2E = 1.4426950408889634f;
    float am[4]; bool okl = true;
    #pragma unroll
    for (int s = 0; s < 4; s++){
        int n = 4*s + lj;
        float av = -__expf(A_logs[(k*EE + e)*NNS + n]);
        am[s] = av * L2E;
        okl &= fabsf(av + (float)(n+1)) < 1e-4f * (float)(n+1);
    }
    const bool ok = __all_sync(0xffffffffu, okl);

    const int ch = bk*EE + e;
    const long chb = (long)ch*LL;
    const float* __restrict__ pd = g_delta + chb;
    const float* __restrict__ pu = g_du    + chb;
    const float* __restrict__ pb = g_B4 + (long)bk*LL*16;
    const float* __restrict__ pc = g_C4 + (long)bk*LL*16;
    float* __restrict__ py = g_y + (long)bk*LL*EE;

    const int l0 = chunk*CHL;
    const float am0 = am[0];

    // ---- sweep 1: local (h_fin, Sdd); last chunk's carry is never used ----
    if (chunk < NCH-1){
        float h0=0.f, h1=0.f, h2=0.f, h3=0.f, sdd = 0.f;
        if (ok){
            for (int l = l0; l < l0 + CHL; l += 4){
                float4 d4 = *(const float4*)(pd + l);
                float4 u4 = *(const float4*)(pu + l);
                float dd[4] = {d4.x, d4.y, d4.z, d4.w};
                float uu[4] = {u4.x, u4.y, u4.z, u4.w};
                #pragma unroll
                for (int s = 0; s < 4; s++){
                    float4 b4 = *(const float4*)(pb + (l+s)*16 + lj*4);
                    float t  = ex2f(dd[s]*am0);
                    float q4 = __shfl_sync(0xffffffffu, t, 3, 4);
                    float dA1 = t*q4, dA2 = dA1*q4, dA3 = dA2*q4;
                    float us = uu[s];
                    h0 = fmaf(t,   h0, us*b4.x);
                    h1 = fmaf(dA1, h1, us*b4.y);
                    h2 = fmaf(dA2, h2, us*b4.z);
                    h3 = fmaf(dA3, h3, us*b4.w);
                }
                sdd += dd[0] + dd[1] + dd[2] + dd[3];
            }
        } else {
            #pragma unroll 1
            for (int l = l0; l < l0 + CHL; l += 4){
                float4 d4 = *(const float4*)(pd + l);
                float4 u4 = *(const float4*)(pu + l);
                float dd[4] = {d4.x, d4.y, d4.z, d4.w};
                float uu[4] = {u4.x, u4.y, u4.z, u4.w};
                #pragma unroll
                for (int s = 0; s < 4; s++){
                    float4 b4 = *(const float4*)(pb + (l+s)*16 + lj*4);
                    float us = uu[s];
                    h0 = fmaf(ex2f(dd[s]*am[0]), h0, us*b4.x);
                    h1 = fmaf(ex2f(dd[s]*am[1]), h1, us*b4.y);
                    h2 = fmaf(ex2f(dd[s]*am[2]), h2, us*b4.z);
                    h3 = fmaf(ex2f(dd[s]*am[3]), h3, us*b4.w);
                }
                sdd += dd[0] + dd[1] + dd[2] + dd[3];
            }
        }
        *(float4*)&hf_s[chunk][lane*4] = make_float4(h0, h1, h2, h3);
        if (lj == 0) sdd_s[chunk][lane >> 2] = sdd;
    }
    __syncthreads();

    // ---- in-block carry propagation: 128 threads, 15 sequential steps ----
    if (threadIdx.x < 128){
        const int slot = threadIdx.x;            // = lane*4 + q
        const int plane = slot >> 2;             // producing lane
        const int q  = slot & 3;                 // h register index (state s)
        const int el = plane >> 2;               // chain within group
        const int pj = plane & 3;                // lj of producing lane
        const int n  = 4*q + pj;
        const int eF = (cidx - bk*24)*8 + el;
        float a = -__expf(A_logs[(k*EE + eF)*NNS + n]);
        float h = 0.f;
        #pragma unroll
        for (int c = 0; c < NCH; c++){
            hi_s[c][slot] = h;
            if (c < NCH-1)
                h = hf_s[c][slot] + __expf(a*sdd_s[c][el])*h;
        }
    }
    __syncthreads();

    // ---- sweep 2: full scan with y output ----
    float4 h4 = *(const float4*)&hi_s[chunk][lane*4];
    float h0 = h4.x, h1 = h4.y, h2 = h4.z, h3 = h4.w;

    if (ok){
        for (int l = l0; l < l0 + CHL; l += 4){
            float4 d4 = *(const float4*)(pd + l);
            float4 u4 = *(const float4*)(pu + l);
            float dd[4] = {d4.x, d4.y, d4.z, d4.w};
            float uu[4] = {u4.x, u4.y, u4.z, u4.w};
            float ysv = 0.f;
            #pragma unroll
            for (int s = 0; s < 4; s++){
                float4 b4 = *(const float4*)(pb + (l+s)*16 + lj*4);
                float4 c4 = *(const float4*)(pc + (l+s)*16 + lj*4);
                float t  = ex2f(dd[s]*am0);
                float q4 = __shfl_sync(0xffffffffu, t, 3, 4);
                float dA1 = t*q4, dA2 = dA1*q4, dA3 = dA2*q4;
                float us = uu[s];
                h0 = fmaf(t,   h0, us*b4.x);
                h1 = fmaf(dA1, h1, us*b4.y);
                h2 = fmaf(dA2, h2, us*b4.z);
                h3 = fmaf(dA3, h3, us*b4.w);
                float p = h0*c4.x;
                p = fmaf(h1, c4.y, p);
                p = fmaf(h2, c4.z, p);
                p = fmaf(h3, c4.w, p);
                p += __shfl_xor_sync(0xffffffffu, p, 1);
                p += __shfl_xor_sync(0xffffffffu, p, 2);
                if (lj == s) ysv = p;
            }
            py[(long)(l + lj)*EE + e] = ysv;
        }
    } else {
        #pragma unroll 1
        for (int l = l0; l < l0 + CHL; l += 4){
            float4 d4 = *(const float4*)(pd + l);
            float4 u4 = *(const float4*)(pu + l);
            float dd[4] = {d4.x, d4.y, d4.z, d4.w};
            float uu[4] = {u4.x, u4.y, u4.z, u4.w};
            float ysv = 0.f;
            #pragma unroll
            for (int s = 0; s < 4; s++){
                float4 b4 = *(const float4*)(pb + (l+s)*16 + lj*4);
                float4 c4 = *(const float4*)(pc + (l+s)*16 + lj*4);
                float us = uu[s];
                h0 = fmaf(ex2f(dd[s]*am[0]), h0, us*b4.x);
                h1 = fmaf(ex2f(dd[s]*am[1]), h1, us*b4.y);
                h2 = fmaf(ex2f(dd[s]*am[2]), h2, us*b4.z);
                h3 = fmaf(ex2f(dd[s]*am[3]), h3, us*b4.w);
                float p = h0*c4.x;
                p = fmaf(h1, c4.y, p);
                p = fmaf(h2, c4.z, p);
                p = fmaf(h3, c4.w, p);
                p += __shfl_xor_sync(0xffffffffu, p, 1);
                p += __shfl_xor_sync(0xffffffffu, p, 2);
                if (lj == s) ysv = p;
            }
            py[(long)(l + lj)*EE + e] = ysv;
        }
    }
}

// ------------------------- merge + D*xc + LayerNorm + gate ------------------
// block = 32 l x 8 threads; all reads are contiguous 192-float rows
__global__ void __launch_bounds__(256) k_merge(const float* __restrict__ Ds, const float* __restrict__ gamma,
                        const float* __restrict__ beta)
{
    __shared__ float sumD[EE];
    const int l0 = blockIdx.x * 32;
    const int b  = blockIdx.y;
    const int t  = threadIdx.x;
    if (t < EE) sumD[t] = Ds[t] + Ds[EE + t] + Ds[2*EE + t] + Ds[3*EE + t];
    __syncthreads();

    const int li = t >> 3, ts = t & 7;
    const int l  = l0 + li;
    const int lw = (l & 63)*64 + (l >> 6);

    const float* __restrict__ y0p = g_y + ((long)(b*4 + 0)*LL + l)*EE;
    const float* __restrict__ y1p = g_y + ((long)(b*4 + 1)*LL + lw)*EE;
    const float* __restrict__ y2p = g_y + ((long)(b*4 + 2)*LL + (LL-1-l))*EE;
    const float* __restrict__ y3p = g_y + ((long)(b*4 + 3)*LL + (LL-1-lw))*EE;
    const float* __restrict__ xcp = g_xc + (long)(b*LL + l)*EE;
    const float* __restrict__ zp  = g_z  + (long)(b*LL + l)*EE;
    float* __restrict__ ymp = g_ym + (long)(b*LL + l)*EE;

    float v[6][4];
    float s1 = 0.f, s2 = 0.f;
    #pragma unroll
    for (int m = 0; m < 6; m++){
        int e4 = (ts + 8*m)*4;
        float4 a0 = *(const float4*)(y0p + e4);
        float4 a1 = *(const float4*)(y1p + e4);
        float4 a2 = *(const float4*)(y2p + e4);
        float4 a3 = *(const float4*)(y3p + e4);
        float4 xc = *(const float4*)(xcp + e4);
        float4 sd = *(const float4*)(&sumD[e4]);
        v[m][0] = a0.x + a1.x + a2.x + a3.x + sd.x*xc.x;
        v[m][1] = a0.y + a1.y + a2.y + a3.y + sd.y*xc.y;
        v[m][2] = a0.z + a1.z + a2.z + a3.z + sd.z*xc.z;
        v[m][3] = a0.w + a1.w + a2.w + a3.w + sd.w*xc.w;
        #pragma unroll
        for (int q = 0; q < 4; q++){ s1 += v[m][q]; s2 += v[m][q]*v[m][q]; }
    }
    #pragma unroll
    for (int o = 1; o < 8; o <<= 1){
        s1 += __shfl_xor_sync(0xffffffffu, s1, o);
        s2 += __shfl_xor_sync(0xffffffffu, s2, o);
    }
    const float inv = 1.f / (float)EE;
    float mu = s1 * inv;
    float var = s2 * inv - mu*mu;
    float rstd = rsqrtf(var + 1e-5f);

    #pragma unroll
    for (int m = 0; m < 6; m++){
        int e4 = (ts + 8*m)*4;
        float4 gm = *(const float4*)(gamma + e4);
        float4 bt = *(const float4*)(beta + e4);
        float4 zz = *(const float4*)(zp + e4);
        float4 o4;
        o4.x = ((v[m][0]-mu)*rstd*gm.x + bt.x) * zz.x;
        o4.y = ((v[m][1]-mu)*rstd*gm.y + bt.y) * zz.y;
        o4.z = ((v[m][2]-mu)*rstd*gm.z + bt.z) * zz.z;
        o4.w = ((v[m][3]-mu)*rstd*gm.w + bt.w) * zz.w;
        *(float4*)(ymp + e4) = o4;
    }
}

// ------------------------- launcher -----------------------------------------
extern "C" void kernel_launch(void* const* d_in, const int* in_sizes, int n_in,
                              void* d_out, int out_size)
{
    const float* x    = (const float*)d_in[0];
    const float* ipw  = (const float*)d_in[1];
    const float* cw   = (const float*)d_in[2];
    const float* cb   = (const float*)d_in[3];
    const float* xpw  = (const float*)d_in[4];
    const float* dtw  = (const float*)d_in[5];
    const float* dtb  = (const float*)d_in[6];
    const float* alog = (const float*)d_in[7];
    const float* Ds   = (const float*)d_in[8];
    const float* lng  = (const float*)d_in[9];
    const float* lnb  = (const float*)d_in[10];
    const float* opw  = (const float*)d_in[11];
    float* out = (float*)d_out;

    k_gemm<DM, 1><<<dim3(128, 6), 256>>>(x, ipw, nullptr, 2*EE);
    k_conv<<<dim3(4, 64, BB), 256>>>(cw, cb);
    k_gemm<EE, 0><<<dim3(128, 3), 256>>>(nullptr, xpw, nullptr, C152);
    k_prep<<<BB*KK*128, 256>>>(dtw, dtb);
    k_scan<<<384, 512>>>(alog);
    k_merge<<<dim3(128, BB), 256>>>(Ds, lng, lnb);
    k_gemm<EE, 2><<<dim3(128, 2), 256>>>(nullptr, opw, out, DM);
}

// round 9
// speedup vs baseline: 1.2111x; 1.1612x over previous
#include <cuda_runtime.h>

#define BB 4
#define HHH 64
#define LL 4096
#define EE 192
#define NNS 16
#define RR 6
#define KK 4
#define DM 96
#define BL (BB*LL)
#define C152 152
#define NCH 16
#define CHL 256   // LL/NCH

typedef unsigned long long u64;

// ------------------------- device scratch (no allocations) ------------------
__device__ float g_xx[BL*EE];
__device__ float g_z [BL*EE];
__device__ float g_xc[BL*EE];
__device__ float g_P [BL*C152];
__device__ float g_delta[16*EE*LL];
__device__ float g_du   [16*EE*LL];
__device__ float g_B4[16*LL*16];
__device__ float g_C4[16*LL*16];
__device__ float g_y [16*LL*EE];       // (bk, l, e)
__device__ float g_ym[BL*EE];
// chunked-scan carries: chain = bk*EE+e in [0,3072); state slot np = lj*4+s
__device__ float g_hfin[3072*NCH*16];
__device__ float g_Sdd [3072*NCH];

__device__ __forceinline__ float ex2f(float x){
    float y; asm("ex2.approx.f32 %0, %1;" : "=f"(y) : "f"(x)); return y;
}
__device__ __forceinline__ float siluf(float x){
    return x / (1.f + __expf(-x));
}
__device__ __forceinline__ float softplusf(float x){
    return fmaxf(x, 0.f) + __logf(1.f + __expf(-fabsf(x)));
}
__device__ __forceinline__ u64 fma2(u64 a, u64 b, u64 c){
    u64 d; asm("fma.rn.f32x2 %0, %1, %2, %3;" : "=l"(d) : "l"(a), "l"(b), "l"(c));
    return d;
}
__device__ __forceinline__ u64 pack2(float x, float y){
    u64 d; asm("mov.b64 %0, {%1, %2};" : "=l"(d) : "f"(x), "f"(y));
    return d;
}
__device__ __forceinline__ void unpack2(u64 v, float& lo, float& hi){
    asm("mov.b64 {%0, %1}, %2;" : "=f"(lo), "=f"(hi) : "l"(v));
}

// ------------------------- tiled GEMM: out[m,n] = sum_k X[m,k]*W[n,k] -------
// 128x64 tile, 256 threads, 8x4 micro-tile, f32x2 packed accumulation
template<int KD, int MODE>
__global__ void __launch_bounds__(256)
k_gemm(const float* __restrict__ Xp, const float* __restrict__ W,
       float* __restrict__ Out, int Nn)
{
    __shared__ float Xs[32][132];
    __shared__ float Ws[32][68];
    const float* __restrict__ X = (MODE==0) ? (const float*)g_xc
                                : (MODE==2) ? (const float*)g_ym : Xp;
    const int m0 = blockIdx.x * 128;
    const int n0 = blockIdx.y * 64;
    const int t  = threadIdx.x;
    const int ty = t >> 4, tx = t & 15;
    u64 acc2[4][4];
    #pragma unroll
    for (int i=0;i<4;i++)
        #pragma unroll
        for (int j=0;j<4;j++) acc2[i][j] = 0ull;

    const int lc4 = (t & 7) * 4;
    const int lr0 = t >> 3;

    for (int kc = 0; kc < KD/32; kc++){
        __syncthreads();
        #pragma unroll
        for (int i = 0; i < 4; i++){
            int r = lr0 + 32*i;
            float4 v = *(const float4*)&X[(m0+r)*KD + kc*32 + lc4];
            Xs[lc4+0][r] = v.x; Xs[lc4+1][r] = v.y;
            Xs[lc4+2][r] = v.z; Xs[lc4+3][r] = v.w;
        }
        #pragma unroll
        for (int i = 0; i < 2; i++){
            int r = lr0 + 32*i;
            int nr = n0 + r;
            float4 v = make_float4(0.f,0.f,0.f,0.f);
            if (nr < Nn) v = *(const float4*)&W[nr*KD + kc*32 + lc4];
            Ws[lc4+0][r] = v.x; Ws[lc4+1][r] = v.y;
            Ws[lc4+2][r] = v.z; Ws[lc4+3][r] = v.w;
        }
        __syncthreads();
        #pragma unroll
        for (int k = 0; k < 32; k++){
            const u64* xp = (const u64*)&Xs[k][ty*8];
            u64 x2[4] = {xp[0], xp[1], xp[2], xp[3]};
            float4 wv = *(const float4*)&Ws[k][tx*4];
            u64 w2[4] = {pack2(wv.x,wv.x), pack2(wv.y,wv.y),
                         pack2(wv.z,wv.z), pack2(wv.w,wv.w)};
            #pragma unroll
            for (int i=0;i<4;i++)
                #pragma unroll
                for (int j=0;j<4;j++) acc2[i][j] = fma2(x2[i], w2[j], acc2[i][j]);
        }
    }
    #pragma unroll
    for (int i=0;i<4;i++){
        #pragma unroll
        for (int j=0;j<4;j++){
            float lo, hi;
            unpack2(acc2[i][j], lo, hi);
            int n = n0 + tx*4 + j;
            int mA = m0 + ty*8 + 2*i;
            #pragma unroll
            for (int pp = 0; pp < 2; pp++){
                int m = mA + pp;
                float v = pp ? hi : lo;
                if (MODE == 1){
                    if (n < EE) g_xx[m*EE + n] = v;
                    else        g_z [m*EE + n - EE] = siluf(v);
                } else if (MODE == 0){
                    if (n < Nn) g_P[m*C152 + n] = v;
                } else {
                    if (n < Nn) Out[m*Nn + n] = v;
                }
            }
        }
    }
}

// ------------------------- depthwise 3x3 conv + bias + silu -----------------
__global__ void __launch_bounds__(256) k_conv(const float* __restrict__ cw, const float* __restrict__ cb)
{
    __shared__ float xs_s[3][64][48];
    __shared__ float cw_s[48][9];
    const int e0 = blockIdx.x * 48;
    const int h  = blockIdx.y;
    const int b  = blockIdx.z;
    const int t  = threadIdx.x;

    for (int idx = t; idx < 3*64*48; idx += 256){
        int row = idx / (64*48);
        int rem = idx - row*(64*48);
        int w  = rem / 48;
        int ec = rem - w*48;
        int hh = h + row - 1;
        float v = 0.f;
        if (hh >= 0 && hh < HHH)
            v = g_xx[(b*LL + hh*64 + w)*EE + e0 + ec];
        xs_s[row][w][ec] = v;
    }
    for (int idx = t; idx < 48*9; idx += 256){
        int ec = idx / 9, q = idx - ec*9;
        cw_s[ec][q] = cw[(e0+ec)*9 + q];
    }
    __syncthreads();

    for (int o = t; o < 64*48; o += 256){
        int w  = o / 48;
        int ec = o - w*48;
        float acc = cb[e0+ec];
        #pragma unroll
        for (int dh = 0; dh < 3; dh++){
            #pragma unroll
            for (int dw = 0; dw < 3; dw++){
                int ww = w + dw - 1;
                if (ww >= 0 && ww < 64)
                    acc = fmaf(xs_s[dh][ww][ec], cw_s[ec][dh*3+dw], acc);
            }
        }
        g_xc[(b*LL + h*64 + w)*EE + e0 + ec] = siluf(acc);
    }
}

// ------------------------- prep: delta/du + B4/C4 ---------------------------
// B4/C4 slot layout per l: np = lj*4 + s  <->  state n = 4*s + lj
__global__ void __launch_bounds__(256) k_prep(const float* __restrict__ dtw, const float* __restrict__ dtb)
{
    __shared__ float Pt[32][39];
    __shared__ float xr[32][193];
    __shared__ float dtws[EE*RR];
    __shared__ float dtbs[EE];
    __shared__ int   clm[32];
    const int bid = blockIdx.x;
    const int lt = bid & 127;
    const int k  = (bid >> 7) & 3;
    const int b  = bid >> 9;
    const int l0 = lt * 32;
    const int t  = threadIdx.x;

    if (t < 32){
        int l = l0 + t, cl;
        if (k == 0)      cl = l;
        else if (k == 1) cl = (l & 63)*64 + (l >> 6);
        else if (k == 2) cl = (LL-1) - l;
        else { int lp = (LL-1) - l; cl = (lp & 63)*64 + (lp >> 6); }
        clm[t] = cl;
    }
    for (int idx = t; idx < EE*RR; idx += 256) dtws[idx] = dtw[k*EE*RR + idx];
    for (int idx = t; idx < EE;    idx += 256) dtbs[idx] = dtb[k*EE + idx];
    __syncthreads();
    for (int idx = t; idx < 32*38; idx += 256){
        int r = idx / 38, c = idx - r*38;
        Pt[r][c] = g_P[(b*LL + clm[r])*C152 + k*38 + c];
    }
    for (int idx = t; idx < 32*48; idx += 256){
        int r = idx / 48, c = idx - r*48;
        float4 v = *(const float4*)&g_xc[(b*LL + clm[r])*EE + c*4];
        xr[r][c*4+0] = v.x; xr[r][c*4+1] = v.y;
        xr[r][c*4+2] = v.z; xr[r][c*4+3] = v.w;
    }
    __syncthreads();

    const int warp = t >> 5, lane = t & 31;
    const int bk = b*KK + k;
    for (int e = warp; e < EE; e += 8){
        float acc = dtbs[e];
        #pragma unroll
        for (int r = 0; r < RR; r++) acc = fmaf(Pt[lane][r], dtws[e*RR + r], acc);
        float dl = softplusf(acc);
        float u  = xr[lane][e];
        int idx = (bk*EE + e)*LL + l0 + lane;
        g_delta[idx] = dl;
        g_du[idx]    = dl * u;
    }
    for (int idx = t; idx < 32*16; idx += 256){
        int pos = idx >> 4, np = idx & 15;
        int n = 4*(np & 3) + (np >> 2);     // state index for slot np
        int o = (bk*LL + l0 + pos)*16 + np;
        g_B4[o] = Pt[pos][6  + n];
        g_C4[o] = Pt[pos][22 + n];
    }
}

// ------------------------- scan pass 1: per-chunk local (h_fin, Sdd) --------
// warp = 8 chains (same bk, consecutive e); 4 lanes/chain, 4 states/lane.
// chunks 0..14 only. grid 720 blocks x 8 warps = 5760 warps.
__global__ void __launch_bounds__(256) k_scan1(const float* __restrict__ A_logs)
{
    const int W = blockIdx.x*8 + (threadIdx.x >> 5);   // [0, 5760)
    const int lane = threadIdx.x & 31;
    const int cidx  = W / 15;          // chain group [0,384)
    const int chunk = W - cidx*15;     // [0,15)
    const int bk = cidx / 24;
    const int e  = (cidx - bk*24)*8 + (lane >> 2);
    const int lj = lane & 3;
    const int k  = bk & 3;

    const float L2E = 1.4426950408889634f;
    float am[4]; bool okl = true;
    #pragma unroll
    for (int s = 0; s < 4; s++){
        int n = 4*s + lj;
        float av = -__expf(A_logs[(k*EE + e)*NNS + n]);
        am[s] = av * L2E;
        okl &= fabsf(av + (float)(n+1)) < 1e-4f * (float)(n+1);
    }
    const bool ok = __all_sync(0xffffffffu, okl);

    const int ch = bk*EE + e;
    const long chb = (long)ch*LL;
    const float* __restrict__ pd = g_delta + chb;
    const float* __restrict__ pu = g_du    + chb;
    const float* __restrict__ pb = g_B4 + (long)bk*LL*16;

    float h0=0.f, h1=0.f, h2=0.f, h3=0.f, sdd = 0.f;
    const int l0 = chunk*CHL;
    const float am0 = am[0];

    if (ok){
        for (int l = l0; l < l0 + CHL; l += 4){
            float4 d4 = *(const float4*)(pd + l);
            float4 u4 = *(const float4*)(pu + l);
            float dd[4] = {d4.x, d4.y, d4.z, d4.w};
            float uu[4] = {u4.x, u4.y, u4.z, u4.w};
            #pragma unroll
            for (int s = 0; s < 4; s++){
                float4 b4 = *(const float4*)(pb + (l+s)*16 + lj*4);
                float t  = ex2f(dd[s]*am0);
                float q4 = __shfl_sync(0xffffffffu, t, 3, 4);
                float dA1 = t*q4, dA2 = dA1*q4, dA3 = dA2*q4;
                float us = uu[s];
                h0 = fmaf(t,   h0, us*b4.x);
                h1 = fmaf(dA1, h1, us*b4.y);
                h2 = fmaf(dA2, h2, us*b4.z);
                h3 = fmaf(dA3, h3, us*b4.w);
            }
            sdd += dd[0] + dd[1] + dd[2] + dd[3];
        }
    } else {
        #pragma unroll 1
        for (int l = l0; l < l0 + CHL; l += 4){
            float4 d4 = *(const float4*)(pd + l);
            float4 u4 = *(const float4*)(pu + l);
            float dd[4] = {d4.x, d4.y, d4.z, d4.w};
            float uu[4] = {u4.x, u4.y, u4.z, u4.w};
            #pragma unroll
            for (int s = 0; s < 4; s++){
                float4 b4 = *(const float4*)(pb + (l+s)*16 + lj*4);
                float us = uu[s];
                h0 = fmaf(ex2f(dd[s]*am[0]), h0, us*b4.x);
                h1 = fmaf(ex2f(dd[s]*am[1]), h1, us*b4.y);
                h2 = fmaf(ex2f(dd[s]*am[2]), h2, us*b4.z);
                h3 = fmaf(ex2f(dd[s]*am[3]), h3, us*b4.w);
            }
            sdd += dd[0] + dd[1] + dd[2] + dd[3];
        }
    }
    int hb = (ch*NCH + chunk)*16 + lj*4;
    *(float4*)&g_hfin[hb] = make_float4(h0, h1, h2, h3);
    if (lj == 0) g_Sdd[ch*NCH + chunk] = sdd;
}

// ------------------------- scan pass 2: inline lookback + full scan ---------
// all 16 chunks. grid 768 blocks x 8 warps = 6144 warps.
// carry for chunk c is rebuilt per-warp from g_hfin/g_Sdd (written by k_scan1).
__global__ void __launch_bounds__(256) k_scan2(const float* __restrict__ A_logs)
{
    const int W = blockIdx.x*8 + (threadIdx.x >> 5);   // [0, 6144)
    const int lane = threadIdx.x & 31;
    const int cidx  = W >> 4;
    const int chunk = W & 15;
    const int bk = cidx / 24;
    const int e  = (cidx - bk*24)*8 + (lane >> 2);
    const int lj = lane & 3;
    const int k  = bk & 3;

    const float L2E = 1.4426950408889634f;
    float am[4]; bool okl = true;
    #pragma unroll
    for (int s = 0; s < 4; s++){
        int n = 4*s + lj;
        float av = -__expf(A_logs[(k*EE + e)*NNS + n]);
        am[s] = av * L2E;
        okl &= fabsf(av + (float)(n+1)) < 1e-4f * (float)(n+1);
    }
    const bool ok = __all_sync(0xffffffffu, okl);

    const int ch = bk*EE + e;
    const long chb = (long)ch*LL;
    const float* __restrict__ pd = g_delta + chb;
    const float* __restrict__ pu = g_du    + chb;
    const float* __restrict__ pb = g_B4 + (long)bk*LL*16;
    const float* __restrict__ pc = g_C4 + (long)bk*LL*16;
    float* __restrict__ py = g_y + (long)bk*LL*EE;

    // ---- inline lookback: rebuild incoming carry from chunk-local results --
    float h0 = 0.f, h1 = 0.f, h2 = 0.f, h3 = 0.f;
    {
        const float* __restrict__ hfp = g_hfin + (long)(ch*NCH)*16 + lj*4;
        const float* __restrict__ sdp = g_Sdd + ch*NCH;
        #pragma unroll 1
        for (int c = 0; c < chunk; c++){
            float4 hf = *(const float4*)(hfp + c*16);
            float S = sdp[c];
            h0 = fmaf(ex2f(S*am[0]), h0, hf.x);
            h1 = fmaf(ex2f(S*am[1]), h1, hf.y);
            h2 = fmaf(ex2f(S*am[2]), h2, hf.z);
            h3 = fmaf(ex2f(S*am[3]), h3, hf.w);
        }
    }

    const int l0 = chunk*CHL;
    const float am0 = am[0];

    if (ok){
        for (int l = l0; l < l0 + CHL; l += 4){
            float4 d4 = *(const float4*)(pd + l);
            float4 u4 = *(const float4*)(pu + l);
            float dd[4] = {d4.x, d4.y, d4.z, d4.w};
            float uu[4] = {u4.x, u4.y, u4.z, u4.w};
            float ysv = 0.f;
            #pragma unroll
            for (int s = 0; s < 4; s++){
                float4 b4 = *(const float4*)(pb + (l+s)*16 + lj*4);
                float4 c4 = *(const float4*)(pc + (l+s)*16 + lj*4);
                float t  = ex2f(dd[s]*am0);
                float q4 = __shfl_sync(0xffffffffu, t, 3, 4);
                float dA1 = t*q4, dA2 = dA1*q4, dA3 = dA2*q4;
                float us = uu[s];
                h0 = fmaf(t,   h0, us*b4.x);
                h1 = fmaf(dA1, h1, us*b4.y);
                h2 = fmaf(dA2, h2, us*b4.z);
                h3 = fmaf(dA3, h3, us*b4.w);
                float p = h0*c4.x;
                p = fmaf(h1, c4.y, p);
                p = fmaf(h2, c4.z, p);
                p = fmaf(h3, c4.w, p);
                p += __shfl_xor_sync(0xffffffffu, p, 1);
                p += __shfl_xor_sync(0xffffffffu, p, 2);
                if (lj == s) ysv = p;
            }
            py[(long)(l + lj)*EE + e] = ysv;
        }
    } else {
        #pragma unroll 1
        for (int l = l0; l < l0 + CHL; l += 4){
            float4 d4 = *(const float4*)(pd + l);
            float4 u4 = *(const float4*)(pu + l);
            float dd[4] = {d4.x, d4.y, d4.z, d4.w};
            float uu[4] = {u4.x, u4.y, u4.z, u4.w};
            float ysv = 0.f;
            #pragma unroll
            for (int s = 0; s < 4; s++){
                float4 b4 = *(const float4*)(pb + (l+s)*16 + lj*4);
                float4 c4 = *(const float4*)(pc + (l+s)*16 + lj*4);
                float us = uu[s];
                h0 = fmaf(ex2f(dd[s]*am[0]), h0, us*b4.x);
                h1 = fmaf(ex2f(dd[s]*am[1]), h1, us*b4.y);
                h2 = fmaf(ex2f(dd[s]*am[2]), h2, us*b4.z);
                h3 = fmaf(ex2f(dd[s]*am[3]), h3, us*b4.w);
                float p = h0*c4.x;
                p = fmaf(h1, c4.y, p);
                p = fmaf(h2, c4.z, p);
                p = fmaf(h3, c4.w, p);
                p += __shfl_xor_sync(0xffffffffu, p, 1);
                p += __shfl_xor_sync(0xffffffffu, p, 2);
                if (lj == s) ysv = p;
            }
            py[(long)(l + lj)*EE + e] = ysv;
        }
    }
}

// ------------------------- merge + D*xc + LayerNorm + gate ------------------
// block = 32 l x 8 threads; all reads are contiguous 192-float rows
__global__ void __launch_bounds__(256) k_merge(const float* __restrict__ Ds, const float* __restrict__ gamma,
                        const float* __restrict__ beta)
{
    __shared__ float sumD[EE];
    const int l0 = blockIdx.x * 32;
    const int b  = blockIdx.y;
    const int t  = threadIdx.x;
    if (t < EE) sumD[t] = Ds[t] + Ds[EE + t] + Ds[2*EE + t] + Ds[3*EE + t];
    __syncthreads();

    const int li = t >> 3, ts = t & 7;
    const int l  = l0 + li;
    const int lw = (l & 63)*64 + (l >> 6);

    const float* __restrict__ y0p = g_y + ((long)(b*4 + 0)*LL + l)*EE;
    const float* __restrict__ y1p = g_y + ((long)(b*4 + 1)*LL + lw)*EE;
    const float* __restrict__ y2p = g_y + ((long)(b*4 + 2)*LL + (LL-1-l))*EE;
    const float* __restrict__ y3p = g_y + ((long)(b*4 + 3)*LL + (LL-1-lw))*EE;
    const float* __restrict__ xcp = g_xc + (long)(b*LL + l)*EE;
    const float* __restrict__ zp  = g_z  + (long)(b*LL + l)*EE;
    float* __restrict__ ymp = g_ym + (long)(b*LL + l)*EE;

    float v[6][4];
    float s1 = 0.f, s2 = 0.f;
    #pragma unroll
    for (int m = 0; m < 6; m++){
        int e4 = (ts + 8*m)*4;
        float4 a0 = *(const float4*)(y0p + e4);
        float4 a1 = *(const float4*)(y1p + e4);
        float4 a2 = *(const float4*)(y2p + e4);
        float4 a3 = *(const float4*)(y3p + e4);
        float4 xc = *(const float4*)(xcp + e4);
        float4 sd = *(const float4*)(&sumD[e4]);
        v[m][0] = a0.x + a1.x + a2.x + a3.x + sd.x*xc.x;
        v[m][1] = a0.y + a1.y + a2.y + a3.y + sd.y*xc.y;
        v[m][2] = a0.z + a1.z + a2.z + a3.z + sd.z*xc.z;
        v[m][3] = a0.w + a1.w + a2.w + a3.w + sd.w*xc.w;
        #pragma unroll
        for (int q = 0; q < 4; q++){ s1 += v[m][q]; s2 += v[m][q]*v[m][q]; }
    }
    #pragma unroll
    for (int o = 1; o < 8; o <<= 1){
        s1 += __shfl_xor_sync(0xffffffffu, s1, o);
        s2 += __shfl_xor_sync(0xffffffffu, s2, o);
    }
    const float inv = 1.f / (float)EE;
    float mu = s1 * inv;
    float var = s2 * inv - mu*mu;
    float rstd = rsqrtf(var + 1e-5f);

    #pragma unroll
    for (int m = 0; m < 6; m++){
        int e4 = (ts + 8*m)*4;
        float4 gm = *(const float4*)(gamma + e4);
        float4 bt = *(const float4*)(beta + e4);
        float4 zz = *(const float4*)(zp + e4);
        float4 o4;
        o4.x = ((v[m][0]-mu)*rstd*gm.x + bt.x) * zz.x;
        o4.y = ((v[m][1]-mu)*rstd*gm.y + bt.y) * zz.y;
        o4.z = ((v[m][2]-mu)*rstd*gm.z + bt.z) * zz.z;
        o4.w = ((v[m][3]-mu)*rstd*gm.w + bt.w) * zz.w;
        *(float4*)(ymp + e4) = o4;
    }
}

// ------------------------- launcher -----------------------------------------
extern "C" void kernel_launch(void* const* d_in, const int* in_sizes, int n_in,
                              void* d_out, int out_size)
{
    const float* x    = (const float*)d_in[0];
    const float* ipw  = (const float*)d_in[1];
    const float* cw   = (const float*)d_in[2];
    const float* cb   = (const float*)d_in[3];
    const float* xpw  = (const float*)d_in[4];
    const float* dtw  = (const float*)d_in[5];
    const float* dtb  = (const float*)d_in[6];
    const float* alog = (const float*)d_in[7];
    const float* Ds   = (const float*)d_in[8];
    const float* lng  = (const float*)d_in[9];
    const float* lnb  = (const float*)d_in[10];
    const float* opw  = (const float*)d_in[11];
    float* out = (float*)d_out;

    k_gemm<DM, 1><<<dim3(128, 6), 256>>>(x, ipw, nullptr, 2*EE);
    k_conv<<<dim3(4, 64, BB), 256>>>(cw, cb);
    k_gemm<EE, 0><<<dim3(128, 3), 256>>>(nullptr, xpw, nullptr, C152);
    k_prep<<<BB*KK*128, 256>>>(dtw, dtb);
    k_scan1<<<720, 256>>>(alog);
    k_scan2<<<768, 256>>>(alog);
    k_merge<<<dim3(128, BB), 256>>>(Ds, lng, lnb);
    k_gemm<EE, 2><<<dim3(128, 2), 256>>>(nullptr, opw, out, DM);
}

// round 10
// speedup vs baseline: 1.2854x; 1.0614x over previous
#include <cuda_runtime.h>

#define BB 4
#define HHH 64
#define LL 4096
#define EE 192
#define NNS 16
#define RR 6
#define KK 4
#define DM 96
#define BL (BB*LL)
#define C152 152
#define NCH 32
#define CHL 128   // LL/NCH

typedef unsigned long long u64;

// ------------------------- device scratch (no allocations) ------------------
__device__ float g_xx[BL*EE];
__device__ float g_z [BL*EE];
__device__ float g_xc[BL*EE];
__device__ float g_P [BL*C152];
__device__ float g_delta[16*EE*LL];
__device__ float g_du   [16*EE*LL];
__device__ float g_B4[16*LL*16];
__device__ float g_C4[16*LL*16];
__device__ float g_y [16*LL*EE];       // (bk, l, e)
__device__ float g_ym[BL*EE];
// chunked-scan carries: chain = bk*EE+e in [0,3072); state slot np = lj*4+s
__device__ float g_hfin[3072*NCH*16];
__device__ float g_hin [3072*NCH*16];
__device__ float g_Sdd [3072*NCH];

__device__ __forceinline__ float ex2f(float x){
    float y; asm("ex2.approx.f32 %0, %1;" : "=f"(y) : "f"(x)); return y;
}
__device__ __forceinline__ float siluf(float x){
    return x / (1.f + __expf(-x));
}
__device__ __forceinline__ float softplusf(float x){
    return fmaxf(x, 0.f) + __logf(1.f + __expf(-fabsf(x)));
}
__device__ __forceinline__ u64 fma2(u64 a, u64 b, u64 c){
    u64 d; asm("fma.rn.f32x2 %0, %1, %2, %3;" : "=l"(d) : "l"(a), "l"(b), "l"(c));
    return d;
}
__device__ __forceinline__ u64 pack2(float x, float y){
    u64 d; asm("mov.b64 %0, {%1, %2};" : "=l"(d) : "f"(x), "f"(y));
    return d;
}
__device__ __forceinline__ void unpack2(u64 v, float& lo, float& hi){
    asm("mov.b64 {%0, %1}, %2;" : "=f"(lo), "=f"(hi) : "l"(v));
}

// ------------------------- tiled GEMM: out[m,n] = sum_k X[m,k]*W[n,k] -------
// 128x64 tile, 256 threads, 8x4 micro-tile, f32x2 packed accumulation,
// register-prefetch software pipeline over k-tiles.
template<int KD, int MODE>
__global__ void __launch_bounds__(256)
k_gemm(const float* __restrict__ Xp, const float* __restrict__ W,
       float* __restrict__ Out, int Nn)
{
    __shared__ float Xs[32][132];
    __shared__ float Ws[32][68];
    const float* __restrict__ X = (MODE==0) ? (const float*)g_xc
                                : (MODE==2) ? (const float*)g_ym : Xp;
    const int m0 = blockIdx.x * 128;
    const int n0 = blockIdx.y * 64;
    const int t  = threadIdx.x;
    const int ty = t >> 4, tx = t & 15;
    u64 acc2[4][4];
    #pragma unroll
    for (int i=0;i<4;i++)
        #pragma unroll
        for (int j=0;j<4;j++) acc2[i][j] = 0ull;

    const int lc4 = (t & 7) * 4;
    const int lr0 = t >> 3;
    const int NKC = KD/32;

    float4 xv[4], wv2[2];
    // prologue: load k-tile 0 into registers
    #pragma unroll
    for (int i = 0; i < 4; i++)
        xv[i] = *(const float4*)&X[(m0 + lr0 + 32*i)*KD + lc4];
    #pragma unroll
    for (int i = 0; i < 2; i++){
        int nr = n0 + lr0 + 32*i;
        wv2[i] = (nr < Nn) ? *(const float4*)&W[nr*KD + lc4]
                           : make_float4(0.f,0.f,0.f,0.f);
    }

    #pragma unroll
    for (int kc = 0; kc < NKC; kc++){
        // store current tile to smem
        #pragma unroll
        for (int i = 0; i < 4; i++){
            int r = lr0 + 32*i;
            Xs[lc4+0][r] = xv[i].x; Xs[lc4+1][r] = xv[i].y;
            Xs[lc4+2][r] = xv[i].z; Xs[lc4+3][r] = xv[i].w;
        }
        #pragma unroll
        for (int i = 0; i < 2; i++){
            int r = lr0 + 32*i;
            Ws[lc4+0][r] = wv2[i].x; Ws[lc4+1][r] = wv2[i].y;
            Ws[lc4+2][r] = wv2[i].z; Ws[lc4+3][r] = wv2[i].w;
        }
        __syncthreads();

        // prefetch next k-tile into registers (overlaps with compute)
        if (kc + 1 < NKC){
            #pragma unroll
            for (int i = 0; i < 4; i++)
                xv[i] = *(const float4*)&X[(m0 + lr0 + 32*i)*KD + (kc+1)*32 + lc4];
            #pragma unroll
            for (int i = 0; i < 2; i++){
                int nr = n0 + lr0 + 32*i;
                wv2[i] = (nr < Nn) ? *(const float4*)&W[nr*KD + (kc+1)*32 + lc4]
                                   : make_float4(0.f,0.f,0.f,0.f);
            }
        }

        #pragma unroll
        for (int k = 0; k < 32; k++){
            const u64* xp = (const u64*)&Xs[k][ty*8];
            u64 x2[4] = {xp[0], xp[1], xp[2], xp[3]};
            float4 wv = *(const float4*)&Ws[k][tx*4];
            u64 w2[4] = {pack2(wv.x,wv.x), pack2(wv.y,wv.y),
                         pack2(wv.z,wv.z), pack2(wv.w,wv.w)};
            #pragma unroll
            for (int i=0;i<4;i++)
                #pragma unroll
                for (int j=0;j<4;j++) acc2[i][j] = fma2(x2[i], w2[j], acc2[i][j]);
        }
        __syncthreads();
    }
    #pragma unroll
    for (int i=0;i<4;i++){
        #pragma unroll
        for (int j=0;j<4;j++){
            float lo, hi;
            unpack2(acc2[i][j], lo, hi);
            int n = n0 + tx*4 + j;
            int mA = m0 + ty*8 + 2*i;
            #pragma unroll
            for (int pp = 0; pp < 2; pp++){
                int m = mA + pp;
                float v = pp ? hi : lo;
                if (MODE == 1){
                    if (n < EE) g_xx[m*EE + n] = v;
                    else        g_z [m*EE + n - EE] = siluf(v);
                } else if (MODE == 0){
                    if (n < Nn) g_P[m*C152 + n] = v;
                } else {
                    if (n < Nn) Out[m*Nn + n] = v;
                }
            }
        }
    }
}

// ------------------------- depthwise 3x3 conv + bias + silu -----------------
__global__ void __launch_bounds__(256) k_conv(const float* __restrict__ cw, const float* __restrict__ cb)
{
    __shared__ float xs_s[3][64][48];
    __shared__ float cw_s[48][9];
    const int e0 = blockIdx.x * 48;
    const int h  = blockIdx.y;
    const int b  = blockIdx.z;
    const int t  = threadIdx.x;

    for (int idx = t; idx < 3*64*48; idx += 256){
        int row = idx / (64*48);
        int rem = idx - row*(64*48);
        int w  = rem / 48;
        int ec = rem - w*48;
        int hh = h + row - 1;
        float v = 0.f;
        if (hh >= 0 && hh < HHH)
            v = g_xx[(b*LL + hh*64 + w)*EE + e0 + ec];
        xs_s[row][w][ec] = v;
    }
    for (int idx = t; idx < 48*9; idx += 256){
        int ec = idx / 9, q = idx - ec*9;
        cw_s[ec][q] = cw[(e0+ec)*9 + q];
    }
    __syncthreads();

    for (int o = t; o < 64*48; o += 256){
        int w  = o / 48;
        int ec = o - w*48;
        float acc = cb[e0+ec];
        #pragma unroll
        for (int dh = 0; dh < 3; dh++){
            #pragma unroll
            for (int dw = 0; dw < 3; dw++){
                int ww = w + dw - 1;
                if (ww >= 0 && ww < 64)
                    acc = fmaf(xs_s[dh][ww][ec], cw_s[ec][dh*3+dw], acc);
            }
        }
        g_xc[(b*LL + h*64 + w)*EE + e0 + ec] = siluf(acc);
    }
}

// ------------------------- prep: delta/du + B4/C4 ---------------------------
// B4/C4 slot layout per l: np = lj*4 + s  <->  state n = 4*s + lj
__global__ void __launch_bounds__(256) k_prep(const float* __restrict__ dtw, const float* __restrict__ dtb)
{
    __shared__ float Pt[32][39];
    __shared__ float xr[32][193];
    __shared__ float dtws[EE*RR];
    __shared__ float dtbs[EE];
    __shared__ int   clm[32];
    const int bid = blockIdx.x;
    const int lt = bid & 127;
    const int k  = (bid >> 7) & 3;
    const int b  = bid >> 9;
    const int l0 = lt * 32;
    const int t  = threadIdx.x;

    if (t < 32){
        int l = l0 + t, cl;
        if (k == 0)      cl = l;
        else if (k == 1) cl = (l & 63)*64 + (l >> 6);
        else if (k == 2) cl = (LL-1) - l;
        else { int lp = (LL-1) - l; cl = (lp & 63)*64 + (lp >> 6); }
        clm[t] = cl;
    }
    for (int idx = t; idx < EE*RR; idx += 256) dtws[idx] = dtw[k*EE*RR + idx];
    for (int idx = t; idx < EE;    idx += 256) dtbs[idx] = dtb[k*EE + idx];
    __syncthreads();
    for (int idx = t; idx < 32*38; idx += 256){
        int r = idx / 38, c = idx - r*38;
        Pt[r][c] = g_P[(b*LL + clm[r])*C152 + k*38 + c];
    }
    for (int idx = t; idx < 32*48; idx += 256){
        int r = idx / 48, c = idx - r*48;
        float4 v = *(const float4*)&g_xc[(b*LL + clm[r])*EE + c*4];
        xr[r][c*4+0] = v.x; xr[r][c*4+1] = v.y;
        xr[r][c*4+2] = v.z; xr[r][c*4+3] = v.w;
    }
    __syncthreads();

    const int warp = t >> 5, lane = t & 31;
    const int bk = b*KK + k;
    for (int e = warp; e < EE; e += 8){
        float acc = dtbs[e];
        #pragma unroll
        for (int r = 0; r < RR; r++) acc = fmaf(Pt[lane][r], dtws[e*RR + r], acc);
        float dl = softplusf(acc);
        float u  = xr[lane][e];
        int idx = (bk*EE + e)*LL + l0 + lane;
        g_delta[idx] = dl;
        g_du[idx]    = dl * u;
    }
    for (int idx = t; idx < 32*16; idx += 256){
        int pos = idx >> 4, np = idx & 15;
        int n = 4*(np & 3) + (np >> 2);     // state index for slot np
        int o = (bk*LL + l0 + pos)*16 + np;
        g_B4[o] = Pt[pos][6  + n];
        g_C4[o] = Pt[pos][22 + n];
    }
}

// ------------------------- scan pass 1: per-chunk local (h_fin, Sdd) --------
// warp = 8 chains (same bk, consecutive e); 4 lanes/chain, 4 states/lane.
// chunks 0..30 only. grid 1488 blocks x 8 warps = 11904 warps.
__global__ void __launch_bounds__(256) k_scan1(const float* __restrict__ A_logs)
{
    const int W = blockIdx.x*8 + (threadIdx.x >> 5);   // [0, 11904)
    const int lane = threadIdx.x & 31;
    const int cidx  = W / 31;          // chain group [0,384)
    const int chunk = W - cidx*31;     // [0,31)
    const int bk = cidx / 24;
    const int e  = (cidx - bk*24)*8 + (lane >> 2);
    const int lj = lane & 3;
    const int k  = bk & 3;

    const float L2E = 1.4426950408889634f;
    float am[4]; bool okl = true;
    #pragma unroll
    for (int s = 0; s < 4; s++){
        int n = 4*s + lj;
        float av = -__expf(A_logs[(k*EE + e)*NNS + n]);
        am[s] = av * L2E;
        okl &= fabsf(av + (float)(n+1)) < 1e-4f * (float)(n+1);
    }
    const bool ok = __all_sync(0xffffffffu, okl);

    const int ch = bk*EE + e;
    const long chb = (long)ch*LL;
    const float* __restrict__ pd = g_delta + chb;
    const float* __restrict__ pu = g_du    + chb;
    const float* __restrict__ pb = g_B4 + (long)bk*LL*16;

    float h0=0.f, h1=0.f, h2=0.f, h3=0.f, sdd = 0.f;
    const int l0 = chunk*CHL;
    const float am0 = am[0];

    if (ok){
        for (int l = l0; l < l0 + CHL; l += 4){
            float4 d4 = *(const float4*)(pd + l);
            float4 u4 = *(const float4*)(pu + l);
            float dd[4] = {d4.x, d4.y, d4.z, d4.w};
            float uu[4] = {u4.x, u4.y, u4.z, u4.w};
            #pragma unroll
            for (int s = 0; s < 4; s++){
                float4 b4 = *(const float4*)(pb + (l+s)*16 + lj*4);
                float t  = ex2f(dd[s]*am0);
                float q4 = __shfl_sync(0xffffffffu, t, 3, 4);
                float dA1 = t*q4, dA2 = dA1*q4, dA3 = dA2*q4;
                float us = uu[s];
                h0 = fmaf(t,   h0, us*b4.x);
                h1 = fmaf(dA1, h1, us*b4.y);
                h2 = fmaf(dA2, h2, us*b4.z);
                h3 = fmaf(dA3, h3, us*b4.w);
            }
            sdd += dd[0] + dd[1] + dd[2] + dd[3];
        }
    } else {
        #pragma unroll 1
        for (int l = l0; l < l0 + CHL; l += 4){
            float4 d4 = *(const float4*)(pd + l);
            float4 u4 = *(const float4*)(pu + l);
            float dd[4] = {d4.x, d4.y, d4.z, d4.w};
            float uu[4] = {u4.x, u4.y, u4.z, u4.w};
            #pragma unroll
            for (int s = 0; s < 4; s++){
                float4 b4 = *(const float4*)(pb + (l+s)*16 + lj*4);
                float us = uu[s];
                h0 = fmaf(ex2f(dd[s]*am[0]), h0, us*b4.x);
                h1 = fmaf(ex2f(dd[s]*am[1]), h1, us*b4.y);
                h2 = fmaf(ex2f(dd[s]*am[2]), h2, us*b4.z);
                h3 = fmaf(ex2f(dd[s]*am[3]), h3, us*b4.w);
            }
            sdd += dd[0] + dd[1] + dd[2] + dd[3];
        }
    }
    int hb = (ch*NCH + chunk)*16 + lj*4;
    *(float4*)&g_hfin[hb] = make_float4(h0, h1, h2, h3);
    if (lj == 0) g_Sdd[ch*NCH + chunk] = sdd;
}

// ------------------------- scan mid: carry propagation ----------------------
// thread = (chain, np). grid 192 x 256.
__global__ void __launch_bounds__(256) k_scanmid(const float* __restrict__ A_logs)
{
    const int tid = blockIdx.x*256 + threadIdx.x;   // [0, 49152)
    const int ch = tid >> 4;
    const int np = tid & 15;
    const int n  = 4*(np & 3) + (np >> 2);
    const int e  = ch % EE;
    const int k  = (ch / EE) & 3;
    float a = -__expf(A_logs[(k*EE + e)*NNS + n]);

    float h = 0.f;
    #pragma unroll
    for (int c = 0; c < NCH; c++){
        g_hin[(ch*NCH + c)*16 + np] = h;
        if (c < NCH-1){
            float hf = g_hfin[(ch*NCH + c)*16 + np];
            float S = g_Sdd[ch*NCH + c];
            h = hf + __expf(a*S)*h;
        }
    }
}

// ------------------------- scan pass 2: full scan, y in (bk,l,e) ------------
// all 32 chunks. grid 1536 blocks x 8 warps = 12288 warps.
__global__ void __launch_bounds__(256) k_scan2(const float* __restrict__ A_logs)
{
    const int W = blockIdx.x*8 + (threadIdx.x >> 5);   // [0, 12288)
    const int lane = threadIdx.x & 31;
    const int cidx  = W >> 5;
    const int chunk = W & 31;
    const int bk = cidx / 24;
    const int e  = (cidx - bk*24)*8 + (lane >> 2);
    const int lj = lane & 3;
    const int k  = bk & 3;

    const float L2E = 1.4426950408889634f;
    float am[4]; bool okl = true;
    #pragma unroll
    for (int s = 0; s < 4; s++){
        int n = 4*s + lj;
        float av = -__expf(A_logs[(k*EE + e)*NNS + n]);
        am[s] = av * L2E;
        okl &= fabsf(av + (float)(n+1)) < 1e-4f * (float)(n+1);
    }
    const bool ok = __all_sync(0xffffffffu, okl);

    const int ch = bk*EE + e;
    const long chb = (long)ch*LL;
    const float* __restrict__ pd = g_delta + chb;
    const float* __restrict__ pu = g_du    + chb;
    const float* __restrict__ pb = g_B4 + (long)bk*LL*16;
    const float* __restrict__ pc = g_C4 + (long)bk*LL*16;
    float* __restrict__ py = g_y + (long)bk*LL*EE;

    float4 h4 = *(const float4*)&g_hin[(ch*NCH + chunk)*16 + lj*4];
    float h0 = h4.x, h1 = h4.y, h2 = h4.z, h3 = h4.w;
    const int l0 = chunk*CHL;
    const float am0 = am[0];

    if (ok){
        for (int l = l0; l < l0 + CHL; l += 4){
            float4 d4 = *(const float4*)(pd + l);
            float4 u4 = *(const float4*)(pu + l);
            float dd[4] = {d4.x, d4.y, d4.z, d4.w};
            float uu[4] = {u4.x, u4.y, u4.z, u4.w};
            float ysv = 0.f;
            #pragma unroll
            for (int s = 0; s < 4; s++){
                float4 b4 = *(const float4*)(pb + (l+s)*16 + lj*4);
                float4 c4 = *(const float4*)(pc + (l+s)*16 + lj*4);
                float t  = ex2f(dd[s]*am0);
                float q4 = __shfl_sync(0xffffffffu, t, 3, 4);
                float dA1 = t*q4, dA2 = dA1*q4, dA3 = dA2*q4;
                float us = uu[s];
                h0 = fmaf(t,   h0, us*b4.x);
                h1 = fmaf(dA1, h1, us*b4.y);
                h2 = fmaf(dA2, h2, us*b4.z);
                h3 = fmaf(dA3, h3, us*b4.w);
                float p = h0*c4.x;
                p = fmaf(h1, c4.y, p);
                p = fmaf(h2, c4.z, p);
                p = fmaf(h3, c4.w, p);
                p += __shfl_xor_sync(0xffffffffu, p, 1);
                p += __shfl_xor_sync(0xffffffffu, p, 2);
                if (lj == s) ysv = p;
            }
            py[(long)(l + lj)*EE + e] = ysv;
        }
    } else {
        #pragma unroll 1
        for (int l = l0; l < l0 + CHL; l += 4){
            float4 d4 = *(const float4*)(pd + l);
            float4 u4 = *(const float4*)(pu + l);
            float dd[4] = {d4.x, d4.y, d4.z, d4.w};
            float uu[4] = {u4.x, u4.y, u4.z, u4.w};
            float ysv = 0.f;
            #pragma unroll
            for (int s = 0; s < 4; s++){
                float4 b4 = *(const float4*)(pb + (l+s)*16 + lj*4);
                float4 c4 = *(const float4*)(pc + (l+s)*16 + lj*4);
                float us = uu[s];
                h0 = fmaf(ex2f(dd[s]*am[0]), h0, us*b4.x);
                h1 = fmaf(ex2f(dd[s]*am[1]), h1, us*b4.y);
                h2 = fmaf(ex2f(dd[s]*am[2]), h2, us*b4.z);
                h3 = fmaf(ex2f(dd[s]*am[3]), h3, us*b4.w);
                float p = h0*c4.x;
                p = fmaf(h1, c4.y, p);
                p = fmaf(h2, c4.z, p);
                p = fmaf(h3, c4.w, p);
                p += __shfl_xor_sync(0xffffffffu, p, 1);
                p += __shfl_xor_sync(0xffffffffu, p, 2);
                if (lj == s) ysv = p;
            }
            py[(long)(l + lj)*EE + e] = ysv;
        }
    }
}

// ------------------------- merge + D*xc + LayerNorm + gate ------------------
// block = 32 l x 8 threads; all reads are contiguous 192-float rows
__global__ void __launch_bounds__(256) k_merge(const float* __restrict__ Ds, const float* __restrict__ gamma,
                        const float* __restrict__ beta)
{
    __shared__ float sumD[EE];
    const int l0 = blockIdx.x * 32;
    const int b  = blockIdx.y;
    const int t  = threadIdx.x;
    if (t < EE) sumD[t] = Ds[t] + Ds[EE + t] + Ds[2*EE + t] + Ds[3*EE + t];
    __syncthreads();

    const int li = t >> 3, ts = t & 7;
    const int l  = l0 + li;
    const int lw = (l & 63)*64 + (l >> 6);

    const float* __restrict__ y0p = g_y + ((long)(b*4 + 0)*LL + l)*EE;
    const float* __restrict__ y1p = g_y + ((long)(b*4 + 1)*LL + lw)*EE;
    const float* __restrict__ y2p = g_y + ((long)(b*4 + 2)*LL + (LL-1-l))*EE;
    const float* __restrict__ y3p = g_y + ((long)(b*4 + 3)*LL + (LL-1-lw))*EE;
    const float* __restrict__ xcp = g_xc + (long)(b*LL + l)*EE;
    const float* __restrict__ zp  = g_z  + (long)(b*LL + l)*EE;
    float* __restrict__ ymp = g_ym + (long)(b*LL + l)*EE;

    float v[6][4];
    float s1 = 0.f, s2 = 0.f;
    #pragma unroll
    for (int m = 0; m < 6; m++){
        int e4 = (ts + 8*m)*4;
        float4 a0 = *(const float4*)(y0p + e4);
        float4 a1 = *(const float4*)(y1p + e4);
        float4 a2 = *(const float4*)(y2p + e4);
        float4 a3 = *(const float4*)(y3p + e4);
        float4 xc = *(const float4*)(xcp + e4);
        float4 sd = *(const float4*)(&sumD[e4]);
        v[m][0] = a0.x + a1.x + a2.x + a3.x + sd.x*xc.x;
        v[m][1] = a0.y + a1.y + a2.y + a3.y + sd.y*xc.y;
        v[m][2] = a0.z + a1.z + a2.z + a3.z + sd.z*xc.z;
        v[m][3] = a0.w + a1.w + a2.w + a3.w + sd.w*xc.w;
        #pragma unroll
        for (int q = 0; q < 4; q++){ s1 += v[m][q]; s2 += v[m][q]*v[m][q]; }
    }
    #pragma unroll
    for (int o = 1; o < 8; o <<= 1){
        s1 += __shfl_xor_sync(0xffffffffu, s1, o);
        s2 += __shfl_xor_sync(0xffffffffu, s2, o);
    }
    const float inv = 1.f / (float)EE;
    float mu = s1 * inv;
    float var = s2 * inv - mu*mu;
    float rstd = rsqrtf(var + 1e-5f);

    #pragma unroll
    for (int m = 0; m < 6; m++){
        int e4 = (ts + 8*m)*4;
        float4 gm = *(const float4*)(gamma + e4);
        float4 bt = *(const float4*)(beta + e4);
        float4 zz = *(const float4*)(zp + e4);
        float4 o4;
        o4.x = ((v[m][0]-mu)*rstd*gm.x + bt.x) * zz.x;
        o4.y = ((v[m][1]-mu)*rstd*gm.y + bt.y) * zz.y;
        o4.z = ((v[m][2]-mu)*rstd*gm.z + bt.z) * zz.z;
        o4.w = ((v[m][3]-mu)*rstd*gm.w + bt.w) * zz.w;
        *(float4*)(ymp + e4) = o4;
    }
}

// ------------------------- launcher -----------------------------------------
extern "C" void kernel_launch(void* const* d_in, const int* in_sizes, int n_in,
                              void* d_out, int out_size)
{
    const float* x    = (const float*)d_in[0];
    const float* ipw  = (const float*)d_in[1];
    const float* cw   = (const float*)d_in[2];
    const float* cb   = (const float*)d_in[3];
    const float* xpw  = (const float*)d_in[4];
    const float* dtw  = (const float*)d_in[5];
    const float* dtb  = (const float*)d_in[6];
    const float* alog = (const float*)d_in[7];
    const float* Ds   = (const float*)d_in[8];
    const float* lng  = (const float*)d_in[9];
    const float* lnb  = (const float*)d_in[10];
    const float* opw  = (const float*)d_in[11];
    float* out = (float*)d_out;

    k_gemm<DM, 1><<<dim3(128, 6), 256>>>(x, ipw, nullptr, 2*EE);
    k_conv<<<dim3(4, 64, BB), 256>>>(cw, cb);
    k_gemm<EE, 0><<<dim3(128, 3), 256>>>(nullptr, xpw, nullptr, C152);
    k_prep<<<BB*KK*128, 256>>>(dtw, dtb);
    k_scan1<<<1488, 256>>>(alog);
    k_scanmid<<<192, 256>>>(alog);
    k_scan2<<<1536, 256>>>(alog);
    k_merge<<<dim3(128, BB), 256>>>(Ds, lng, lnb);
    k_gemm<EE, 2><<<dim3(128, 2), 256>>>(nullptr, opw, out, DM);
}

// round 11
// speedup vs baseline: 1.3403x; 1.0427x over previous
#include <cuda_runtime.h>

#define BB 4
#define HHH 64
#define LL 4096
#define EE 192
#define NNS 16
#define RR 6
#define KK 4
#define DM 96
#define BL (BB*LL)
#define C152 152
#define NCH 32
#define CHL 128   // LL/NCH

typedef unsigned long long u64;

// ------------------------- device scratch (no allocations) ------------------
__device__ float g_xx[BL*EE];
__device__ float g_z [BL*EE];
__device__ float g_xc[BL*EE];
__device__ float g_P [BL*C152];
__device__ float g_delta[16*EE*LL];
__device__ float g_du   [16*EE*LL];
__device__ float g_B4[16*LL*16];
__device__ float g_C4[16*LL*16];
__device__ float g_y [16*LL*EE];       // (bk, l, e)
__device__ float g_ym[BL*EE];
// chunked-scan carries: chain = bk*EE+e in [0,3072); state slot np = lj*4+s
__device__ float g_hfin[3072*NCH*16];
__device__ float g_hin [3072*NCH*16];
__device__ float g_Sdd [3072*NCH];

__device__ __forceinline__ float ex2f(float x){
    float y; asm("ex2.approx.f32 %0, %1;" : "=f"(y) : "f"(x)); return y;
}
__device__ __forceinline__ float siluf(float x){
    return x / (1.f + __expf(-x));
}
__device__ __forceinline__ float softplusf(float x){
    return fmaxf(x, 0.f) + __logf(1.f + __expf(-fabsf(x)));
}
__device__ __forceinline__ u64 fma2(u64 a, u64 b, u64 c){
    u64 d; asm("fma.rn.f32x2 %0, %1, %2, %3;" : "=l"(d) : "l"(a), "l"(b), "l"(c));
    return d;
}
__device__ __forceinline__ u64 pack2(float x, float y){
    u64 d; asm("mov.b64 %0, {%1, %2};" : "=l"(d) : "f"(x), "f"(y));
    return d;
}
__device__ __forceinline__ void unpack2(u64 v, float& lo, float& hi){
    asm("mov.b64 {%0, %1}, %2;" : "=f"(lo), "=f"(hi) : "l"(v));
}

// ------------------------- tiled GEMM: out[m,n] = sum_k X[m,k]*W[n,k] -------
// 128x64 tile, 256 threads, 8x4 micro-tile, f32x2 packed accumulation,
// register-prefetch software pipeline over k-tiles.
template<int KD, int MODE>
__global__ void __launch_bounds__(256)
k_gemm(const float* __restrict__ Xp, const float* __restrict__ W,
       float* __restrict__ Out, int Nn)
{
    __shared__ float Xs[32][132];
    __shared__ float Ws[32][68];
    const float* __restrict__ X = (MODE==0) ? (const float*)g_xc
                                : (MODE==2) ? (const float*)g_ym : Xp;
    const int m0 = blockIdx.x * 128;
    const int n0 = blockIdx.y * 64;
    const int t  = threadIdx.x;
    const int ty = t >> 4, tx = t & 15;
    u64 acc2[4][4];
    #pragma unroll
    for (int i=0;i<4;i++)
        #pragma unroll
        for (int j=0;j<4;j++) acc2[i][j] = 0ull;

    const int lc4 = (t & 7) * 4;
    const int lr0 = t >> 3;
    const int NKC = KD/32;

    float4 xv[4], wv2[2];
    #pragma unroll
    for (int i = 0; i < 4; i++)
        xv[i] = *(const float4*)&X[(m0 + lr0 + 32*i)*KD + lc4];
    #pragma unroll
    for (int i = 0; i < 2; i++){
        int nr = n0 + lr0 + 32*i;
        wv2[i] = (nr < Nn) ? *(const float4*)&W[nr*KD + lc4]
                           : make_float4(0.f,0.f,0.f,0.f);
    }

    #pragma unroll
    for (int kc = 0; kc < NKC; kc++){
        #pragma unroll
        for (int i = 0; i < 4; i++){
            int r = lr0 + 32*i;
            Xs[lc4+0][r] = xv[i].x; Xs[lc4+1][r] = xv[i].y;
            Xs[lc4+2][r] = xv[i].z; Xs[lc4+3][r] = xv[i].w;
        }
        #pragma unroll
        for (int i = 0; i < 2; i++){
            int r = lr0 + 32*i;
            Ws[lc4+0][r] = wv2[i].x; Ws[lc4+1][r] = wv2[i].y;
            Ws[lc4+2][r] = wv2[i].z; Ws[lc4+3][r] = wv2[i].w;
        }
        __syncthreads();

        if (kc + 1 < NKC){
            #pragma unroll
            for (int i = 0; i < 4; i++)
                xv[i] = *(const float4*)&X[(m0 + lr0 + 32*i)*KD + (kc+1)*32 + lc4];
            #pragma unroll
            for (int i = 0; i < 2; i++){
                int nr = n0 + lr0 + 32*i;
                wv2[i] = (nr < Nn) ? *(const float4*)&W[nr*KD + (kc+1)*32 + lc4]
                                   : make_float4(0.f,0.f,0.f,0.f);
            }
        }

        #pragma unroll
        for (int k = 0; k < 32; k++){
            const u64* xp = (const u64*)&Xs[k][ty*8];
            u64 x2[4] = {xp[0], xp[1], xp[2], xp[3]};
            float4 wv = *(const float4*)&Ws[k][tx*4];
            u64 w2[4] = {pack2(wv.x,wv.x), pack2(wv.y,wv.y),
                         pack2(wv.z,wv.z), pack2(wv.w,wv.w)};
            #pragma unroll
            for (int i=0;i<4;i++)
                #pragma unroll
                for (int j=0;j<4;j++) acc2[i][j] = fma2(x2[i], w2[j], acc2[i][j]);
        }
        __syncthreads();
    }
    #pragma unroll
    for (int i=0;i<4;i++){
        #pragma unroll
        for (int j=0;j<4;j++){
            float lo, hi;
            unpack2(acc2[i][j], lo, hi);
            int n = n0 + tx*4 + j;
            int mA = m0 + ty*8 + 2*i;
            #pragma unroll
            for (int pp = 0; pp < 2; pp++){
                int m = mA + pp;
                float v = pp ? hi : lo;
                if (MODE == 1){
                    if (n < EE) g_xx[m*EE + n] = v;
                    else        g_z [m*EE + n - EE] = siluf(v);
                } else if (MODE == 0){
                    if (n < Nn) g_P[m*C152 + n] = v;
                } else {
                    if (n < Nn) Out[m*Nn + n] = v;
                }
            }
        }
    }
}

// ------------------------- depthwise 3x3 conv + bias + silu -----------------
__global__ void __launch_bounds__(256) k_conv(const float* __restrict__ cw, const float* __restrict__ cb)
{
    __shared__ float xs_s[3][64][48];
    __shared__ float cw_s[48][9];
    const int e0 = blockIdx.x * 48;
    const int h  = blockIdx.y;
    const int b  = blockIdx.z;
    const int t  = threadIdx.x;

    for (int idx = t; idx < 3*64*48; idx += 256){
        int row = idx / (64*48);
        int rem = idx - row*(64*48);
        int w  = rem / 48;
        int ec = rem - w*48;
        int hh = h + row - 1;
        float v = 0.f;
        if (hh >= 0 && hh < HHH)
            v = g_xx[(b*LL + hh*64 + w)*EE + e0 + ec];
        xs_s[row][w][ec] = v;
    }
    for (int idx = t; idx < 48*9; idx += 256){
        int ec = idx / 9, q = idx - ec*9;
        cw_s[ec][q] = cw[(e0+ec)*9 + q];
    }
    __syncthreads();

    for (int o = t; o < 64*48; o += 256){
        int w  = o / 48;
        int ec = o - w*48;
        float acc = cb[e0+ec];
        #pragma unroll
        for (int dh = 0; dh < 3; dh++){
            #pragma unroll
            for (int dw = 0; dw < 3; dw++){
                int ww = w + dw - 1;
                if (ww >= 0 && ww < 64)
                    acc = fmaf(xs_s[dh][ww][ec], cw_s[ec][dh*3+dw], acc);
            }
        }
        g_xc[(b*LL + h*64 + w)*EE + e0 + ec] = siluf(acc);
    }
}

// ------------------------- prep: delta/du + B4/C4 ---------------------------
// B4/C4 slot layout per l: np = lj*4 + s  <->  state n = 4*s + lj
__global__ void __launch_bounds__(256) k_prep(const float* __restrict__ dtw, const float* __restrict__ dtb)
{
    __shared__ float Pt[32][39];
    __shared__ float xr[32][193];
    __shared__ float dtws[EE*RR];
    __shared__ float dtbs[EE];
    __shared__ int   clm[32];
    const int bid = blockIdx.x;
    const int lt = bid & 127;
    const int k  = (bid >> 7) & 3;
    const int b  = bid >> 9;
    const int l0 = lt * 32;
    const int t  = threadIdx.x;

    if (t < 32){
        int l = l0 + t, cl;
        if (k == 0)      cl = l;
        else if (k == 1) cl = (l & 63)*64 + (l >> 6);
        else if (k == 2) cl = (LL-1) - l;
        else { int lp = (LL-1) - l; cl = (lp & 63)*64 + (lp >> 6); }
        clm[t] = cl;
    }
    for (int idx = t; idx < EE*RR; idx += 256) dtws[idx] = dtw[k*EE*RR + idx];
    for (int idx = t; idx < EE;    idx += 256) dtbs[idx] = dtb[k*EE + idx];
    __syncthreads();
    for (int idx = t; idx < 32*38; idx += 256){
        int r = idx / 38, c = idx - r*38;
        Pt[r][c] = g_P[(b*LL + clm[r])*C152 + k*38 + c];
    }
    for (int idx = t; idx < 32*48; idx += 256){
        int r = idx / 48, c = idx - r*48;
        float4 v = *(const float4*)&g_xc[(b*LL + clm[r])*EE + c*4];
        xr[r][c*4+0] = v.x; xr[r][c*4+1] = v.y;
        xr[r][c*4+2] = v.z; xr[r][c*4+3] = v.w;
    }
    __syncthreads();

    const int warp = t >> 5, lane = t & 31;
    const int bk = b*KK + k;
    for (int e = warp; e < EE; e += 8){
        float acc = dtbs[e];
        #pragma unroll
        for (int r = 0; r < RR; r++) acc = fmaf(Pt[lane][r], dtws[e*RR + r], acc);
        float dl = softplusf(acc);
        float u  = xr[lane][e];
        int idx = (bk*EE + e)*LL + l0 + lane;
        g_delta[idx] = dl;
        g_du[idx]    = dl * u;
    }
    for (int idx = t; idx < 32*16; idx += 256){
        int pos = idx >> 4, np = idx & 15;
        int n = 4*(np & 3) + (np >> 2);     // state index for slot np
        int o = (bk*LL + l0 + pos)*16 + np;
        g_B4[o] = Pt[pos][6  + n];
        g_C4[o] = Pt[pos][22 + n];
    }
}

// ------------------------- scan pass 1: per-chunk local (h_fin, Sdd) --------
// block = (bk, chunk, e-group-triplet): 8 warps share (bk, chunk), stage B
// into smem once; warp w covers e-group (egb*8+w). chunks 0..30 only.
// grid 16*31*3 = 1488 blocks x 256.
__global__ void __launch_bounds__(256) k_scan1(const float* __restrict__ A_logs)
{
    __shared__ float Bs[CHL*16];       // 8KB

    const int warp = threadIdx.x >> 5;
    const int lane = threadIdx.x & 31;
    int tmp = blockIdx.x;
    const int egb   = tmp % 3;  tmp /= 3;
    const int chunk = tmp % 31; tmp /= 31;
    const int bk    = tmp;
    const int eg = egb*8 + warp;                 // [0,24)
    const int e  = eg*8 + (lane >> 2);
    const int lj = lane & 3;
    const int k  = bk & 3;
    const int t  = threadIdx.x;
    const int l0 = chunk*CHL;

    // stage B tile (contiguous 8KB)
    {
        const float4* src = (const float4*)(g_B4 + ((long)bk*LL + l0)*16);
        float4* dst = (float4*)Bs;
        #pragma unroll
        for (int i = 0; i < 2; i++) dst[t + 256*i] = src[t + 256*i];
    }

    const float L2E = 1.4426950408889634f;
    float am[4]; bool okl = true;
    #pragma unroll
    for (int s = 0; s < 4; s++){
        int n = 4*s + lj;
        float av = -__expf(A_logs[(k*EE + e)*NNS + n]);
        am[s] = av * L2E;
        okl &= fabsf(av + (float)(n+1)) < 1e-4f * (float)(n+1);
    }
    const bool ok = __all_sync(0xffffffffu, okl);

    const int ch = bk*EE + e;
    const long chb = (long)ch*LL;
    const float* __restrict__ pd = g_delta + chb + l0;
    const float* __restrict__ pu = g_du    + chb + l0;

    __syncthreads();

    float h0=0.f, h1=0.f, h2=0.f, h3=0.f, sdd = 0.f;
    const float am0 = am[0];

    if (ok){
        for (int l = 0; l < CHL; l += 4){
            float4 d4 = *(const float4*)(pd + l);
            float4 u4 = *(const float4*)(pu + l);
            float dd[4] = {d4.x, d4.y, d4.z, d4.w};
            float uu[4] = {u4.x, u4.y, u4.z, u4.w};
            #pragma unroll
            for (int s = 0; s < 4; s++){
                float4 b4 = *(const float4*)(Bs + (l+s)*16 + lj*4);
                float tt = ex2f(dd[s]*am0);
                float q4 = __shfl_sync(0xffffffffu, tt, 3, 4);
                float dA1 = tt*q4, dA2 = dA1*q4, dA3 = dA2*q4;
                float us = uu[s];
                h0 = fmaf(tt,  h0, us*b4.x);
                h1 = fmaf(dA1, h1, us*b4.y);
                h2 = fmaf(dA2, h2, us*b4.z);
                h3 = fmaf(dA3, h3, us*b4.w);
            }
            sdd += dd[0] + dd[1] + dd[2] + dd[3];
        }
    } else {
        #pragma unroll 1
        for (int l = 0; l < CHL; l += 4){
            float4 d4 = *(const float4*)(pd + l);
            float4 u4 = *(const float4*)(pu + l);
            float dd[4] = {d4.x, d4.y, d4.z, d4.w};
            float uu[4] = {u4.x, u4.y, u4.z, u4.w};
            #pragma unroll
            for (int s = 0; s < 4; s++){
                float4 b4 = *(const float4*)(Bs + (l+s)*16 + lj*4);
                float us = uu[s];
                h0 = fmaf(ex2f(dd[s]*am[0]), h0, us*b4.x);
                h1 = fmaf(ex2f(dd[s]*am[1]), h1, us*b4.y);
                h2 = fmaf(ex2f(dd[s]*am[2]), h2, us*b4.z);
                h3 = fmaf(ex2f(dd[s]*am[3]), h3, us*b4.w);
            }
            sdd += dd[0] + dd[1] + dd[2] + dd[3];
        }
    }
    int hb = (ch*NCH + chunk)*16 + lj*4;
    *(float4*)&g_hfin[hb] = make_float4(h0, h1, h2, h3);
    if (lj == 0) g_Sdd[ch*NCH + chunk] = sdd;
}

// ------------------------- scan mid: carry propagation ----------------------
// thread = (chain, np). grid 192 x 256.
__global__ void __launch_bounds__(256) k_scanmid(const float* __restrict__ A_logs)
{
    const int tid = blockIdx.x*256 + threadIdx.x;   // [0, 49152)
    const int ch = tid >> 4;
    const int np = tid & 15;
    const int n  = 4*(np & 3) + (np >> 2);
    const int e  = ch % EE;
    const int k  = (ch / EE) & 3;
    float a = -__expf(A_logs[(k*EE + e)*NNS + n]);

    float h = 0.f;
    #pragma unroll
    for (int c = 0; c < NCH; c++){
        g_hin[(ch*NCH + c)*16 + np] = h;
        if (c < NCH-1){
            float hf = g_hfin[(ch*NCH + c)*16 + np];
            float S = g_Sdd[ch*NCH + c];
            h = hf + __expf(a*S)*h;
        }
    }
}

// ------------------------- scan pass 2: full scan, y in (bk,l,e) ------------
// block = (bk, chunk, e-group-triplet): stage B and C into smem.
// all 32 chunks. grid 16*32*3 = 1536 blocks x 256.
__global__ void __launch_bounds__(256) k_scan2(const float* __restrict__ A_logs)
{
    __shared__ float Bs[CHL*16];       // 8KB
    __shared__ float Cs[CHL*16];       // 8KB

    const int warp = threadIdx.x >> 5;
    const int lane = threadIdx.x & 31;
    int tmp = blockIdx.x;
    const int egb   = tmp % 3;  tmp /= 3;
    const int chunk = tmp & 31;
    const int bk    = tmp >> 5;
    const int eg = egb*8 + warp;
    const int e  = eg*8 + (lane >> 2);
    const int lj = lane & 3;
    const int k  = bk & 3;
    const int t  = threadIdx.x;
    const int l0 = chunk*CHL;

    // stage B and C tiles (contiguous 8KB each)
    {
        const float4* srcB = (const float4*)(g_B4 + ((long)bk*LL + l0)*16);
        const float4* srcC = (const float4*)(g_C4 + ((long)bk*LL + l0)*16);
        float4* dstB = (float4*)Bs;
        float4* dstC = (float4*)Cs;
        #pragma unroll
        for (int i = 0; i < 2; i++){
            dstB[t + 256*i] = srcB[t + 256*i];
            dstC[t + 256*i] = srcC[t + 256*i];
        }
    }

    const float L2E = 1.4426950408889634f;
    float am[4]; bool okl = true;
    #pragma unroll
    for (int s = 0; s < 4; s++){
        int n = 4*s + lj;
        float av = -__expf(A_logs[(k*EE + e)*NNS + n]);
        am[s] = av * L2E;
        okl &= fabsf(av + (float)(n+1)) < 1e-4f * (float)(n+1);
    }
    const bool ok = __all_sync(0xffffffffu, okl);

    const int ch = bk*EE + e;
    const long chb = (long)ch*LL;
    const float* __restrict__ pd = g_delta + chb + l0;
    const float* __restrict__ pu = g_du    + chb + l0;
    float* __restrict__ py = g_y + ((long)bk*LL + l0)*EE;

    float4 h4 = *(const float4*)&g_hin[(ch*NCH + chunk)*16 + lj*4];
    float h0 = h4.x, h1 = h4.y, h2 = h4.z, h3 = h4.w;
    const float am0 = am[0];

    __syncthreads();

    if (ok){
        for (int l = 0; l < CHL; l += 4){
            float4 d4 = *(const float4*)(pd + l);
            float4 u4 = *(const float4*)(pu + l);
            float dd[4] = {d4.x, d4.y, d4.z, d4.w};
            float uu[4] = {u4.x, u4.y, u4.z, u4.w};
            float ysv = 0.f;
            #pragma unroll
            for (int s = 0; s < 4; s++){
                float4 b4 = *(const float4*)(Bs + (l+s)*16 + lj*4);
                float4 c4 = *(const float4*)(Cs + (l+s)*16 + lj*4);
                float tt = ex2f(dd[s]*am0);
                float q4 = __shfl_sync(0xffffffffu, tt, 3, 4);
                float dA1 = tt*q4, dA2 = dA1*q4, dA3 = dA2*q4;
                float us = uu[s];
                h0 = fmaf(tt,  h0, us*b4.x);
                h1 = fmaf(dA1, h1, us*b4.y);
                h2 = fmaf(dA2, h2, us*b4.z);
                h3 = fmaf(dA3, h3, us*b4.w);
                float p = h0*c4.x;
                p = fmaf(h1, c4.y, p);
                p = fmaf(h2, c4.z, p);
                p = fmaf(h3, c4.w, p);
                p += __shfl_xor_sync(0xffffffffu, p, 1);
                p += __shfl_xor_sync(0xffffffffu, p, 2);
                if (lj == s) ysv = p;
            }
            py[(long)(l + lj)*EE + e] = ysv;
        }
    } else {
        #pragma unroll 1
        for (int l = 0; l < CHL; l += 4){
            float4 d4 = *(const float4*)(pd + l);
            float4 u4 = *(const float4*)(pu + l);
            float dd[4] = {d4.x, d4.y, d4.z, d4.w};
            float uu[4] = {u4.x, u4.y, u4.z, u4.w};
            float ysv = 0.f;
            #pragma unroll
            for (int s = 0; s < 4; s++){
                float4 b4 = *(const float4*)(Bs + (l+s)*16 + lj*4);
                float4 c4 = *(const float4*)(Cs + (l+s)*16 + lj*4);
                float us = uu[s];
                h0 = fmaf(ex2f(dd[s]*am[0]), h0, us*b4.x);
                h1 = fmaf(ex2f(dd[s]*am[1]), h1, us*b4.y);
                h2 = fmaf(ex2f(dd[s]*am[2]), h2, us*b4.z);
                h3 = fmaf(ex2f(dd[s]*am[3]), h3, us*b4.w);
                float p = h0*c4.x;
                p = fmaf(h1, c4.y, p);
                p = fmaf(h2, c4.z, p);
                p = fmaf(h3, c4.w, p);
                p += __shfl_xor_sync(0xffffffffu, p, 1);
                p += __shfl_xor_sync(0xffffffffu, p, 2);
                if (lj == s) ysv = p;
            }
            py[(long)(l + lj)*EE + e] = ysv;
        }
    }
}

// ------------------------- merge + D*xc + LayerNorm + gate ------------------
// block = 32 l x 8 threads; all reads are contiguous 192-float rows
__global__ void __launch_bounds__(256) k_merge(const float* __restrict__ Ds, const float* __restrict__ gamma,
                        const float* __restrict__ beta)
{
    __shared__ float sumD[EE];
    const int l0 = blockIdx.x * 32;
    const int b  = blockIdx.y;
    const int t  = threadIdx.x;
    if (t < EE) sumD[t] = Ds[t] + Ds[EE + t] + Ds[2*EE + t] + Ds[3*EE + t];
    __syncthreads();

    const int li = t >> 3, ts = t & 7;
    const int l  = l0 + li;
    const int lw = (l & 63)*64 + (l >> 6);

    const float* __restrict__ y0p = g_y + ((long)(b*4 + 0)*LL + l)*EE;
    const float* __restrict__ y1p = g_y + ((long)(b*4 + 1)*LL + lw)*EE;
    const float* __restrict__ y2p = g_y + ((long)(b*4 + 2)*LL + (LL-1-l))*EE;
    const float* __restrict__ y3p = g_y + ((long)(b*4 + 3)*LL + (LL-1-lw))*EE;
    const float* __restrict__ xcp = g_xc + (long)(b*LL + l)*EE;
    const float* __restrict__ zp  = g_z  + (long)(b*LL + l)*EE;
    float* __restrict__ ymp = g_ym + (long)(b*LL + l)*EE;

    float v[6][4];
    float s1 = 0.f, s2 = 0.f;
    #pragma unroll
    for (int m = 0; m < 6; m++){
        int e4 = (ts + 8*m)*4;
        float4 a0 = *(const float4*)(y0p + e4);
        float4 a1 = *(const float4*)(y1p + e4);
        float4 a2 = *(const float4*)(y2p + e4);
        float4 a3 = *(const float4*)(y3p + e4);
        float4 xc = *(const float4*)(xcp + e4);
        float4 sd = *(const float4*)(&sumD[e4]);
        v[m][0] = a0.x + a1.x + a2.x + a3.x + sd.x*xc.x;
        v[m][1] = a0.y + a1.y + a2.y + a3.y + sd.y*xc.y;
        v[m][2] = a0.z + a1.z + a2.z + a3.z + sd.z*xc.z;
        v[m][3] = a0.w + a1.w + a2.w + a3.w + sd.w*xc.w;
        #pragma unroll
        for (int q = 0; q < 4; q++){ s1 += v[m][q]; s2 += v[m][q]*v[m][q]; }
    }
    #pragma unroll
    for (int o = 1; o < 8; o <<= 1){
        s1 += __shfl_xor_sync(0xffffffffu, s1, o);
        s2 += __shfl_xor_sync(0xffffffffu, s2, o);
    }
    const float inv = 1.f / (float)EE;
    float mu = s1 * inv;
    float var = s2 * inv - mu*mu;
    float rstd = rsqrtf(var + 1e-5f);

    #pragma unroll
    for (int m = 0; m < 6; m++){
        int e4 = (ts + 8*m)*4;
        float4 gm = *(const float4*)(gamma + e4);
        float4 bt = *(const float4*)(beta + e4);
        float4 zz = *(const float4*)(zp + e4);
        float4 o4;
        o4.x = ((v[m][0]-mu)*rstd*gm.x + bt.x) * zz.x;
        o4.y = ((v[m][1]-mu)*rstd*gm.y + bt.y) * zz.y;
        o4.z = ((v[m][2]-mu)*rstd*gm.z + bt.z) * zz.z;
        o4.w = ((v[m][3]-mu)*rstd*gm.w + bt.w) * zz.w;
        *(float4*)(ymp + e4) = o4;
    }
}

// ------------------------- launcher -----------------------------------------
extern "C" void kernel_launch(void* const* d_in, const int* in_sizes, int n_in,
                              void* d_out, int out_size)
{
    const float* x    = (const float*)d_in[0];
    const float* ipw  = (const float*)d_in[1];
    const float* cw   = (const float*)d_in[2];
    const float* cb   = (const float*)d_in[3];
    const float* xpw  = (const float*)d_in[4];
    const float* dtw  = (const float*)d_in[5];
    const float* dtb  = (const float*)d_in[6];
    const float* alog = (const float*)d_in[7];
    const float* Ds   = (const float*)d_in[8];
    const float* lng  = (const float*)d_in[9];
    const float* lnb  = (const float*)d_in[10];
    const float* opw  = (const float*)d_in[11];
    float* out = (float*)d_out;

    k_gemm<DM, 1><<<dim3(128, 6), 256>>>(x, ipw, nullptr, 2*EE);
    k_conv<<<dim3(4, 64, BB), 256>>>(cw, cb);
    k_gemm<EE, 0><<<dim3(128, 3), 256>>>(nullptr, xpw, nullptr, C152);
    k_prep<<<BB*KK*128, 256>>>(dtw, dtb);
    k_scan1<<<16*31*3, 256>>>(alog);
    k_scanmid<<<192, 256>>>(alog);
    k_scan2<<<16*32*3, 256>>>(alog);
    k_merge<<<dim3(128, BB), 256>>>(Ds, lng, lnb);
    k_gemm<EE, 2><<<dim3(128, 2), 256>>>(nullptr, opw, out, DM);
}